// round 1
// baseline (speedup 1.0000x reference)
#include <cuda_runtime.h>

#define NSEQ 4096
#define CDIM 512

// Scratch (allocation-free rule: __device__ globals)
__device__ float g_q[CDIM * NSEQ];
__device__ float g_k[CDIM * NSEQ];
__device__ float g_v[CDIM * NSEQ];
__device__ float g_ao[CDIM * NSEQ];

// ---------------------------------------------------------------------------
// Y[o,n] = scale * (sum_c W[o,c] * X[c,n] + bias[o])
// M=512 (o), N=4096 (n), K=512 (c).  BM=BN=64, BK=16, 256 thr, 4x4 micro.
// ---------------------------------------------------------------------------
__global__ __launch_bounds__(256) void gemm_proj(
    const float* __restrict__ W, const float* __restrict__ bias,
    const float* __restrict__ X, float* __restrict__ Y, float scale)
{
    __shared__ float Ws[16][64];
    __shared__ float Xs[16][68];   // pad to 68 for aligned float4 rows

    const int tid = threadIdx.x;
    const int tx = tid & 15, ty = tid >> 4;
    const int o0 = blockIdx.y * 64, n0 = blockIdx.x * 64;

    const int wo = tid >> 2, wc = (tid & 3) << 2;      // W loader mapping
    const int xc = tid >> 4, xn = (tid & 15) << 2;     // X loader mapping

    float acc[4][4];
#pragma unroll
    for (int i = 0; i < 4; i++)
#pragma unroll
        for (int j = 0; j < 4; j++) acc[i][j] = 0.f;

    for (int k0 = 0; k0 < CDIM; k0 += 16) {
        float4 wv = *(const float4*)(W + (size_t)(o0 + wo) * CDIM + k0 + wc);
        Ws[wc + 0][wo] = wv.x;
        Ws[wc + 1][wo] = wv.y;
        Ws[wc + 2][wo] = wv.z;
        Ws[wc + 3][wo] = wv.w;
        float4 xv = *(const float4*)(X + (size_t)(k0 + xc) * NSEQ + n0 + xn);
        *(float4*)(&Xs[xc][xn]) = xv;
        __syncthreads();

#pragma unroll
        for (int c = 0; c < 16; c++) {
            float4 a  = *(const float4*)(&Ws[c][ty << 2]);
            float4 bv = *(const float4*)(&Xs[c][tx << 2]);
            float ar[4] = {a.x, a.y, a.z, a.w};
            float br[4] = {bv.x, bv.y, bv.z, bv.w};
#pragma unroll
            for (int i = 0; i < 4; i++)
#pragma unroll
                for (int j = 0; j < 4; j++)
                    acc[i][j] = fmaf(ar[i], br[j], acc[i][j]);
        }
        __syncthreads();
    }

#pragma unroll
    for (int i = 0; i < 4; i++) {
        int o = o0 + (ty << 2) + i;
        float bb = bias[o];
        float4 outv;
        outv.x = (acc[i][0] + bb) * scale;
        outv.y = (acc[i][1] + bb) * scale;
        outv.z = (acc[i][2] + bb) * scale;
        outv.w = (acc[i][3] + bb) * scale;
        *(float4*)(Y + (size_t)o * NSEQ + n0 + (tx << 2)) = outv;
    }
}

// ---------------------------------------------------------------------------
// Flash attention. Q,K,V,O in (C=512, N=4096) channel-major layout.
// grid = (N/32 q-tiles, 8 heads), block = 128 threads.
// Per block: 32 queries of one head; iterate 64-key tiles with online softmax.
// Thread map (tidy = tid>>4 in 0..7, tidx = tid&15):
//   S phase: rows r0=4*tidy (4), keys kc0=4*tidx (4)  -> 4x4 scores
//   O phase: rows r0 (4),        dims d0=4*tidx (4)  -> 4x4 accumulators
// Ks buffer is reused for P (transposed [k][r], stride 36, padded).
// V stored with float4-granular XOR swizzle for conflict-free LDS.
// ---------------------------------------------------------------------------
__global__ __launch_bounds__(128) void attn_kernel(
    const float* __restrict__ Q, const float* __restrict__ K,
    const float* __restrict__ V, float* __restrict__ O)
{
    __shared__ float Qs[64 * 32];    // Qs[c][q], stride 32
    __shared__ float KPs[64 * 64];   // Ks[c][k] stride 64; reused as P[k][r] stride 36
    __shared__ float Vs[64 * 64];    // swizzled [k][d]
    __shared__ float Ms[32], Ls[32];

    const int tid  = threadIdx.x;
    const int tidx = tid & 15, tidy = tid >> 4;
    const int r0 = tidy << 2;
    const int kc0 = tidx << 2;
    const int d0 = tidx << 2;
    const int q0 = blockIdx.x * 32;
    const int hb = blockIdx.y * 64;   // channel base of this head

    for (int t = tid; t < 64 * 32; t += 128) {
        int c = t >> 5, q = t & 31;
        Qs[t] = Q[(size_t)(hb + c) * NSEQ + q0 + q];
    }
    if (tid < 32) { Ms[tid] = -1e30f; Ls[tid] = 0.f; }

    float oacc[4][4];
#pragma unroll
    for (int i = 0; i < 4; i++)
#pragma unroll
        for (int j = 0; j < 4; j++) oacc[i][j] = 0.f;

    __syncthreads();

    for (int m0 = 0; m0 < NSEQ; m0 += 64) {
        // ---- load K tile [c][k] and V tile (swizzled [k][d]) ----
        for (int t = tid; t < 4096; t += 128) {
            int c = t >> 6, k = t & 63;
            KPs[t] = K[(size_t)(hb + c) * NSEQ + m0 + k];
        }
        for (int t = tid; t < 4096; t += 128) {
            int d = t >> 6, k = t & 63;
            int sw = (d & 3) | (((d >> 2) ^ (k & 15)) << 2);
            Vs[(k << 6) | sw] = V[(size_t)(hb + d) * NSEQ + m0 + k];
        }
        __syncthreads();

        // ---- S = Q^T K (4x4 per thread) ----
        float s[4][4];
#pragma unroll
        for (int i = 0; i < 4; i++)
#pragma unroll
            for (int j = 0; j < 4; j++) s[i][j] = 0.f;

#pragma unroll 8
        for (int c = 0; c < 64; c++) {
            float4 qv = *(const float4*)(Qs + (c << 5) + r0);
            float4 kv = *(const float4*)(KPs + (c << 6) + kc0);
            float qr[4] = {qv.x, qv.y, qv.z, qv.w};
            float kr[4] = {kv.x, kv.y, kv.z, kv.w};
#pragma unroll
            for (int i = 0; i < 4; i++)
#pragma unroll
                for (int j = 0; j < 4; j++)
                    s[i][j] = fmaf(qr[i], kr[j], s[i][j]);
        }

        // ---- online softmax ----
        float tmax[4];
#pragma unroll
        for (int i = 0; i < 4; i++) {
            tmax[i] = s[i][0];
#pragma unroll
            for (int j = 1; j < 4; j++) tmax[i] = fmaxf(tmax[i], s[i][j]);
        }
#pragma unroll
        for (int off = 1; off < 16; off <<= 1)
#pragma unroll
            for (int i = 0; i < 4; i++)
                tmax[i] = fmaxf(tmax[i], __shfl_xor_sync(0xffffffffu, tmax[i], off));

        float newM[4], alpha[4], lsum[4];
#pragma unroll
        for (int i = 0; i < 4; i++) {
            float mo = Ms[r0 + i];
            newM[i] = fmaxf(mo, tmax[i]);
            alpha[i] = __expf(mo - newM[i]);
            lsum[i] = 0.f;
#pragma unroll
            for (int j = 0; j < 4; j++) {
                s[i][j] = __expf(s[i][j] - newM[i]);
                lsum[i] += s[i][j];
            }
        }
#pragma unroll
        for (int off = 1; off < 16; off <<= 1)
#pragma unroll
            for (int i = 0; i < 4; i++)
                lsum[i] += __shfl_xor_sync(0xffffffffu, lsum[i], off);

        __syncwarp();
        if (tidx == 0) {
#pragma unroll
            for (int i = 0; i < 4; i++) {
                Ms[r0 + i] = newM[i];
                Ls[r0 + i] = Ls[r0 + i] * alpha[i] + lsum[i];
            }
        }
        __syncthreads();   // all warps finished reading Ks; Ms/Ls published

        // ---- write P transposed [k][r] (stride 36) into the Ks buffer ----
#pragma unroll
        for (int j = 0; j < 4; j++) {
            float4 pv = make_float4(s[0][j], s[1][j], s[2][j], s[3][j]);
            *(float4*)(KPs + (kc0 + j) * 36 + r0) = pv;
        }
        __syncwarp();      // P rows are produced & consumed within one warp

        // ---- rescale O, accumulate P·V ----
#pragma unroll
        for (int i = 0; i < 4; i++)
#pragma unroll
            for (int j = 0; j < 4; j++) oacc[i][j] *= alpha[i];

#pragma unroll 8
        for (int k = 0; k < 64; k++) {
            float4 pv = *(const float4*)(KPs + k * 36 + r0);
            float4 vv = *(const float4*)(Vs + (k << 6) + ((tidx ^ (k & 15)) << 2));
            float pr[4] = {pv.x, pv.y, pv.z, pv.w};
            float vr[4] = {vv.x, vv.y, vv.z, vv.w};
#pragma unroll
            for (int i = 0; i < 4; i++)
#pragma unroll
                for (int j = 0; j < 4; j++)
                    oacc[i][j] = fmaf(pr[i], vr[j], oacc[i][j]);
        }
        __syncthreads();   // protect KPs/Vs before next tile's loads
    }

    // ---- normalize and write (C,N) layout ----
#pragma unroll
    for (int i = 0; i < 4; i++) {
        float inv = 1.f / Ls[r0 + i];
#pragma unroll
        for (int j = 0; j < 4; j++)
            O[(size_t)(hb + d0 + j) * NSEQ + q0 + r0 + i] = oacc[i][j] * inv;
    }
}

// ---------------------------------------------------------------------------
extern "C" void kernel_launch(void* const* d_in, const int* in_sizes, int n_in,
                              void* d_out, int out_size)
{
    const float* x   = (const float*)d_in[0];
    const float* q_w = (const float*)d_in[1];
    const float* q_b = (const float*)d_in[2];
    const float* k_w = (const float*)d_in[3];
    const float* k_b = (const float*)d_in[4];
    const float* v_w = (const float*)d_in[5];
    const float* v_b = (const float*)d_in[6];
    const float* o_w = (const float*)d_in[7];
    const float* o_b = (const float*)d_in[8];
    float* out = (float*)d_out;

    float *gq, *gk, *gv, *gao;
    cudaGetSymbolAddress((void**)&gq,  g_q);
    cudaGetSymbolAddress((void**)&gk,  g_k);
    cudaGetSymbolAddress((void**)&gv,  g_v);
    cudaGetSymbolAddress((void**)&gao, g_ao);

    dim3 ggrid(NSEQ / 64, CDIM / 64);
    const float kSCALE = 0.125f;   // HEAD_DIM^-0.5, folded into K proj (w & b)

    gemm_proj<<<ggrid, 256>>>(q_w, q_b, x, gq, 1.0f);
    gemm_proj<<<ggrid, 256>>>(k_w, k_b, x, gk, kSCALE);
    gemm_proj<<<ggrid, 256>>>(v_w, v_b, x, gv, 1.0f);

    dim3 agrid(NSEQ / 32, 8);
    attn_kernel<<<agrid, 128>>>(gq, gk, gv, gao);

    gemm_proj<<<ggrid, 256>>>(o_w, o_b, gao, out, 1.0f);
}

// round 4
// speedup vs baseline: 2.2381x; 2.2381x over previous
#include <cuda_runtime.h>

#define NSEQ 4096
#define CDIM 512
#define SQ 68   // smem row stride (floats): 68 % 32 == 4 -> (4g+tg) bank-injective

// Scratch (allocation-free rule: __device__ globals)
__device__ float g_q[CDIM * NSEQ];   // transposed [n][c]
__device__ float g_k[CDIM * NSEQ];   // transposed [n][c]
__device__ float g_v[CDIM * NSEQ];   // natural    [c][n]
__device__ float g_ao[CDIM * NSEQ];  // natural    [c][n]

__device__ __forceinline__ unsigned f2tf(float f) {
    unsigned u;
    asm("cvt.rna.tf32.f32 %0, %1;" : "=r"(u) : "f"(f));
    return u;
}

__device__ __forceinline__ void mma_tf32(
    float& c0, float& c1, float& c2, float& c3,
    unsigned a0, unsigned a1, unsigned a2, unsigned a3,
    unsigned b0, unsigned b1)
{
    asm volatile(
        "mma.sync.aligned.m16n8k8.row.col.f32.tf32.tf32.f32 "
        "{%0,%1,%2,%3},{%4,%5,%6,%7},{%8,%9},{%0,%1,%2,%3};"
        : "+f"(c0), "+f"(c1), "+f"(c2), "+f"(c3)
        : "r"(a0), "r"(a1), "r"(a2), "r"(a3), "r"(b0), "r"(b1));
}

// ---------------------------------------------------------------------------
// Y = scale * (W X + b).  M=512(o), N=4096(n), K=512(c).
// tout=0: Y[o][n] (natural).  tout=1: Y[n][o] (transposed, for Q/K).
// ---------------------------------------------------------------------------
__global__ __launch_bounds__(256) void gemm_proj(
    const float* __restrict__ W, const float* __restrict__ bias,
    const float* __restrict__ X, float* __restrict__ Y, float scale, int tout)
{
    __shared__ float Ws[16][64];
    __shared__ float Xs[16][68];

    const int tid = threadIdx.x;
    const int tx = tid & 15, ty = tid >> 4;
    const int o0 = blockIdx.y * 64, n0 = blockIdx.x * 64;

    const int wo = tid >> 2, wc = (tid & 3) << 2;
    const int xc = tid >> 4, xn = (tid & 15) << 2;

    float acc[4][4];
#pragma unroll
    for (int i = 0; i < 4; i++)
#pragma unroll
        for (int j = 0; j < 4; j++) acc[i][j] = 0.f;

    for (int k0 = 0; k0 < CDIM; k0 += 16) {
        float4 wv = *(const float4*)(W + (size_t)(o0 + wo) * CDIM + k0 + wc);
        Ws[wc + 0][wo] = wv.x;
        Ws[wc + 1][wo] = wv.y;
        Ws[wc + 2][wo] = wv.z;
        Ws[wc + 3][wo] = wv.w;
        float4 xv = *(const float4*)(X + (size_t)(k0 + xc) * NSEQ + n0 + xn);
        *(float4*)(&Xs[xc][xn]) = xv;
        __syncthreads();

#pragma unroll
        for (int c = 0; c < 16; c++) {
            float4 a  = *(const float4*)(&Ws[c][ty << 2]);
            float4 bv = *(const float4*)(&Xs[c][tx << 2]);
            float ar[4] = {a.x, a.y, a.z, a.w};
            float br[4] = {bv.x, bv.y, bv.z, bv.w};
#pragma unroll
            for (int i = 0; i < 4; i++)
#pragma unroll
                for (int j = 0; j < 4; j++)
                    acc[i][j] = fmaf(ar[i], br[j], acc[i][j]);
        }
        __syncthreads();
    }

    if (!tout) {
#pragma unroll
        for (int i = 0; i < 4; i++) {
            int o = o0 + (ty << 2) + i;
            float bb = bias[o];
            float4 outv;
            outv.x = (acc[i][0] + bb) * scale;
            outv.y = (acc[i][1] + bb) * scale;
            outv.z = (acc[i][2] + bb) * scale;
            outv.w = (acc[i][3] + bb) * scale;
            *(float4*)(Y + (size_t)o * NSEQ + n0 + (tx << 2)) = outv;
        }
    } else {
        float b0 = bias[o0 + (ty << 2) + 0];
        float b1 = bias[o0 + (ty << 2) + 1];
        float b2 = bias[o0 + (ty << 2) + 2];
        float b3 = bias[o0 + (ty << 2) + 3];
#pragma unroll
        for (int j = 0; j < 4; j++) {
            float4 outv;
            outv.x = (acc[0][j] + b0) * scale;
            outv.y = (acc[1][j] + b1) * scale;
            outv.z = (acc[2][j] + b2) * scale;
            outv.w = (acc[3][j] + b3) * scale;
            *(float4*)(Y + (size_t)(n0 + (tx << 2) + j) * CDIM + o0 + (ty << 2)) = outv;
        }
    }
}

// ---------------------------------------------------------------------------
// tf32 mma.sync flash attention.
// QT,KT: [n][c] transposed.  V: [c][n].  O: [c][n].
// grid (NSEQ/64, 8 heads), block 128 (4 warps, 16 q-rows each).
// S[q][k]: A=Qs[q][d] row-major, B(d,k)=Ks[k][d].
// PV as O^T[d][q]: A=Vs[d][k] row-major (natural!), B(k,q)=P[q][k] via shfl repack.
// K and V share one smem buffer (phase-split).
// ---------------------------------------------------------------------------
__global__ __launch_bounds__(128) void attn_mma(
    const float* __restrict__ QT, const float* __restrict__ KT,
    const float* __restrict__ V, float* __restrict__ O)
{
    __shared__ float Qs[64 * SQ];   // [q][d]
    __shared__ float KVs[64 * SQ];  // K-phase: [k][d];  V-phase: [d][k]

    const int tid  = threadIdx.x;
    const int w    = tid >> 5;
    const int lane = tid & 31;
    const int g    = lane >> 2;    // groupID
    const int tg   = lane & 3;     // thread-in-group
    const int q0   = blockIdx.x * 64;
    const int hb   = blockIdx.y * 64;
    const unsigned FULL = 0xffffffffu;

    // ---- load Q tile (tf32-rounded) ----
    for (int t = tid; t < 1024; t += 128) {
        int q = t >> 4, d4 = (t & 15) << 2;
        float4 v = *(const float4*)(QT + (size_t)(q0 + q) * CDIM + hb + d4);
        float* p = Qs + q * SQ + d4;
        p[0] = __uint_as_float(f2tf(v.x));
        p[1] = __uint_as_float(f2tf(v.y));
        p[2] = __uint_as_float(f2tf(v.z));
        p[3] = __uint_as_float(f2tf(v.w));
    }

    float m0 = -1e30f, m1 = -1e30f, l0 = 0.f, l1 = 0.f;
    float oa[4][2][4];
#pragma unroll
    for (int mt = 0; mt < 4; mt++)
#pragma unroll
        for (int np = 0; np < 2; np++)
#pragma unroll
            for (int r = 0; r < 4; r++) oa[mt][np][r] = 0.f;

    __syncthreads();

    const float* qb = Qs + (16 * w + g) * SQ;

    for (int t0 = 0; t0 < NSEQ; t0 += 64) {
        // ---- K phase: KVs[k][d] ----
        for (int t = tid; t < 1024; t += 128) {
            int k = t >> 4, d4 = (t & 15) << 2;
            float4 v = *(const float4*)(KT + (size_t)(t0 + k) * CDIM + hb + d4);
            float* p = KVs + k * SQ + d4;
            p[0] = __uint_as_float(f2tf(v.x));
            p[1] = __uint_as_float(f2tf(v.y));
            p[2] = __uint_as_float(f2tf(v.z));
            p[3] = __uint_as_float(f2tf(v.w));
        }
        __syncthreads();

        // ---- S = Q K^T (per warp: 16q x 64k) ----
        float sc[8][4];
#pragma unroll
        for (int nt = 0; nt < 8; nt++)
#pragma unroll
            for (int r = 0; r < 4; r++) sc[nt][r] = 0.f;

#pragma unroll
        for (int ks = 0; ks < 8; ks++) {
            unsigned a0 = __float_as_uint(qb[8 * ks + tg]);
            unsigned a1 = __float_as_uint(qb[8 * SQ + 8 * ks + tg]);
            unsigned a2 = __float_as_uint(qb[8 * ks + tg + 4]);
            unsigned a3 = __float_as_uint(qb[8 * SQ + 8 * ks + tg + 4]);
#pragma unroll
            for (int nt = 0; nt < 8; nt++) {
                unsigned b0 = __float_as_uint(KVs[(g + 8 * nt) * SQ + 8 * ks + tg]);
                unsigned b1 = __float_as_uint(KVs[(g + 8 * nt) * SQ + 8 * ks + tg + 4]);
                mma_tf32(sc[nt][0], sc[nt][1], sc[nt][2], sc[nt][3],
                         a0, a1, a2, a3, b0, b1);
            }
        }
        __syncthreads();   // done reading K; buffer free for V

        // ---- V phase load: KVs[d][k] ----
        for (int t = tid; t < 1024; t += 128) {
            int d = t >> 4, k4 = (t & 15) << 2;
            float4 v = *(const float4*)(V + (size_t)(hb + d) * NSEQ + t0 + k4);
            float* p = KVs + d * SQ + k4;
            p[0] = __uint_as_float(f2tf(v.x));
            p[1] = __uint_as_float(f2tf(v.y));
            p[2] = __uint_as_float(f2tf(v.z));
            p[3] = __uint_as_float(f2tf(v.w));
        }

        // ---- online softmax (registers; rows q=g and q=g+8) ----
        float mx0 = -1e30f, mx1 = -1e30f;
#pragma unroll
        for (int nt = 0; nt < 8; nt++) {
            mx0 = fmaxf(mx0, fmaxf(sc[nt][0], sc[nt][1]));
            mx1 = fmaxf(mx1, fmaxf(sc[nt][2], sc[nt][3]));
        }
        mx0 = fmaxf(mx0, __shfl_xor_sync(FULL, mx0, 1));
        mx0 = fmaxf(mx0, __shfl_xor_sync(FULL, mx0, 2));
        mx1 = fmaxf(mx1, __shfl_xor_sync(FULL, mx1, 1));
        mx1 = fmaxf(mx1, __shfl_xor_sync(FULL, mx1, 2));

        float nm0 = fmaxf(m0, mx0), nm1 = fmaxf(m1, mx1);
        float al0 = __expf(m0 - nm0), al1 = __expf(m1 - nm1);
        float s0 = 0.f, s1 = 0.f;
#pragma unroll
        for (int nt = 0; nt < 8; nt++) {
            sc[nt][0] = __expf(sc[nt][0] - nm0);
            sc[nt][1] = __expf(sc[nt][1] - nm0);
            sc[nt][2] = __expf(sc[nt][2] - nm1);
            sc[nt][3] = __expf(sc[nt][3] - nm1);
            s0 += sc[nt][0] + sc[nt][1];
            s1 += sc[nt][2] + sc[nt][3];
        }
        s0 += __shfl_xor_sync(FULL, s0, 1);
        s0 += __shfl_xor_sync(FULL, s0, 2);
        s1 += __shfl_xor_sync(FULL, s1, 1);
        s1 += __shfl_xor_sync(FULL, s1, 2);
        l0 = l0 * al0 + s0;
        l1 = l1 * al1 + s1;
        m0 = nm0; m1 = nm1;

        // ---- rescale O accumulators (alpha indexed by q-column) ----
        float av00 = __shfl_sync(FULL, al0, (2 * tg) << 2);
        float av01 = __shfl_sync(FULL, al0, (2 * tg + 1) << 2);
        float av10 = __shfl_sync(FULL, al1, (2 * tg) << 2);
        float av11 = __shfl_sync(FULL, al1, (2 * tg + 1) << 2);
#pragma unroll
        for (int mt = 0; mt < 4; mt++) {
            oa[mt][0][0] *= av00; oa[mt][0][1] *= av01;
            oa[mt][0][2] *= av00; oa[mt][0][3] *= av01;
            oa[mt][1][0] *= av10; oa[mt][1][1] *= av11;
            oa[mt][1][2] *= av10; oa[mt][1][3] *= av11;
        }

        __syncthreads();   // V tile ready

        // ---- O^T += V^T P^T ----
        const int s0l = (g << 2) | (tg >> 1);
        const int s1l = s0l + 2;
#pragma unroll
        for (int ks = 0; ks < 8; ks++) {
            // B-frags for nt'=0 (P rows 0..7): from sc[ks][0/1]
            float y0 = __shfl_sync(FULL, sc[ks][0], s0l);
            float y1 = __shfl_sync(FULL, sc[ks][1], s0l);
            float y2 = __shfl_sync(FULL, sc[ks][0], s1l);
            float y3 = __shfl_sync(FULL, sc[ks][1], s1l);
            unsigned b00 = f2tf((tg & 1) ? y1 : y0);
            unsigned b01 = f2tf((tg & 1) ? y3 : y2);
            // nt'=1 (P rows 8..15): from sc[ks][2/3]
            float z0 = __shfl_sync(FULL, sc[ks][2], s0l);
            float z1 = __shfl_sync(FULL, sc[ks][3], s0l);
            float z2 = __shfl_sync(FULL, sc[ks][2], s1l);
            float z3 = __shfl_sync(FULL, sc[ks][3], s1l);
            unsigned b10 = f2tf((tg & 1) ? z1 : z0);
            unsigned b11 = f2tf((tg & 1) ? z3 : z2);

#pragma unroll
            for (int mt = 0; mt < 4; mt++) {
                const float* vb = KVs + (16 * mt + g) * SQ + 8 * ks;
                unsigned a0 = __float_as_uint(vb[tg]);
                unsigned a1 = __float_as_uint(vb[8 * SQ + tg]);
                unsigned a2 = __float_as_uint(vb[tg + 4]);
                unsigned a3 = __float_as_uint(vb[8 * SQ + tg + 4]);
                mma_tf32(oa[mt][0][0], oa[mt][0][1], oa[mt][0][2], oa[mt][0][3],
                         a0, a1, a2, a3, b00, b01);
                mma_tf32(oa[mt][1][0], oa[mt][1][1], oa[mt][1][2], oa[mt][1][3],
                         a0, a1, a2, a3, b10, b11);
            }
        }
        __syncthreads();   // done reading V before next K load
    }

    // ---- normalize, store O^T frags to O[c][n] ----
    float inv0 = 1.f / l0, inv1 = 1.f / l1;
    float n00 = __shfl_sync(FULL, inv0, (2 * tg) << 2);
    float n01 = __shfl_sync(FULL, inv0, (2 * tg + 1) << 2);
    float n10 = __shfl_sync(FULL, inv1, (2 * tg) << 2);
    float n11 = __shfl_sync(FULL, inv1, (2 * tg + 1) << 2);

#pragma unroll
    for (int mt = 0; mt < 4; mt++) {
#pragma unroll
        for (int np = 0; np < 2; np++) {
            float sa = np ? n10 : n00;
            float sb = np ? n11 : n01;
            int dr = hb + 16 * mt + g;
            int qc = q0 + 16 * w + 8 * np + 2 * tg;
            float2 v0 = make_float2(oa[mt][np][0] * sa, oa[mt][np][1] * sb);
            float2 v1 = make_float2(oa[mt][np][2] * sa, oa[mt][np][3] * sb);
            *(float2*)(O + (size_t)dr * NSEQ + qc)       = v0;
            *(float2*)(O + (size_t)(dr + 8) * NSEQ + qc) = v1;
        }
    }
}

// ---------------------------------------------------------------------------
extern "C" void kernel_launch(void* const* d_in, const int* in_sizes, int n_in,
                              void* d_out, int out_size)
{
    const float* x   = (const float*)d_in[0];
    const float* q_w = (const float*)d_in[1];
    const float* q_b = (const float*)d_in[2];
    const float* k_w = (const float*)d_in[3];
    const float* k_b = (const float*)d_in[4];
    const float* v_w = (const float*)d_in[5];
    const float* v_b = (const float*)d_in[6];
    const float* o_w = (const float*)d_in[7];
    const float* o_b = (const float*)d_in[8];
    float* out = (float*)d_out;

    float *gq, *gk, *gv, *gao;
    cudaGetSymbolAddress((void**)&gq,  g_q);
    cudaGetSymbolAddress((void**)&gk,  g_k);
    cudaGetSymbolAddress((void**)&gv,  g_v);
    cudaGetSymbolAddress((void**)&gao, g_ao);

    dim3 ggrid(NSEQ / 64, CDIM / 64);
    const float kSCALE = 0.125f;   // HEAD_DIM^-0.5 folded into K proj (w & b)

    gemm_proj<<<ggrid, 256>>>(q_w, q_b, x, gq, 1.0f, 1);      // Q transposed
    gemm_proj<<<ggrid, 256>>>(k_w, k_b, x, gk, kSCALE, 1);    // K transposed
    gemm_proj<<<ggrid, 256>>>(v_w, v_b, x, gv, 1.0f, 0);      // V natural

    dim3 agrid(NSEQ / 64, 8);
    attn_mma<<<agrid, 128>>>(gq, gk, gv, gao);

    gemm_proj<<<ggrid, 256>>>(o_w, o_b, gao, out, 1.0f, 0);
}

// round 6
// speedup vs baseline: 3.8732x; 1.7306x over previous
#include <cuda_runtime.h>
#include <cstdint>

#define NSEQ 4096
#define CDIM 512

// Scratch (allocation-free rule: __device__ globals)
__device__ float g_q[CDIM * NSEQ];   // Q^T [n][c], tf32-rounded
__device__ float g_k[CDIM * NSEQ];   // K^T [n][c], scaled by 0.125*log2e, tf32-rounded
__device__ float g_v[CDIM * NSEQ];   // V^T [n][c], tf32-rounded
__device__ float g_ao[CDIM * NSEQ];  // attention out [n][c]

__device__ __forceinline__ unsigned f2tf(float f) {
    unsigned u; asm("cvt.rna.tf32.f32 %0, %1;" : "=r"(u) : "f"(f)); return u;
}
__device__ __forceinline__ float ex2f(float x) {
    float y; asm("ex2.approx.f32 %0, %1;" : "=f"(y) : "f"(x)); return y;
}
__device__ __forceinline__ void cp16(uint32_t dst, const float* src) {
    asm volatile("cp.async.cg.shared.global [%0], [%1], 16;" :: "r"(dst), "l"(src));
}
__device__ __forceinline__ void cp_commit() { asm volatile("cp.async.commit_group;"); }
__device__ __forceinline__ void cp_wait0()  { asm volatile("cp.async.wait_group 0;" ::: "memory"); }

__device__ __forceinline__ void mma_tf32(
    float& c0, float& c1, float& c2, float& c3,
    unsigned a0, unsigned a1, unsigned a2, unsigned a3,
    unsigned b0, unsigned b1)
{
    asm volatile(
        "mma.sync.aligned.m16n8k8.row.col.f32.tf32.tf32.f32 "
        "{%0,%1,%2,%3},{%4,%5,%6,%7},{%8,%9},{%0,%1,%2,%3};"
        : "+f"(c0), "+f"(c1), "+f"(c2), "+f"(c3)
        : "r"(a0), "r"(a1), "r"(a2), "r"(a3), "r"(b0), "r"(b1));
}
#define FB(x) __float_as_uint(x)

// ---------------------------------------------------------------------------
// tf32 MMA projection.  W[o][c], bias[o].
// MODE 0: X = [c][n] global; output Y^T[n][o], values tf32-rounded (Q/K/V).
// MODE 1: X = [n][c] global; output Y[o][n] fp32 (final O projection).
// Block: 128 thr (4 warps), tile 64n x 64o, K-loop over c in 64-chunks.
// ---------------------------------------------------------------------------
template<int MODE>
__global__ __launch_bounds__(128) void gemm_tf32(
    const float* __restrict__ W, const float* __restrict__ bias,
    const float* __restrict__ X, float* __restrict__ Y, float scale)
{
    __shared__ float smp[64 * 68 + 64 * 72];
    float* Ws = smp;             // [o][c] stride 68
    float* Xs = smp + 64 * 68;   // MODE0: [c][n] stride 72 ; MODE1: [n][c] stride 68

    const int tid = threadIdx.x, w = tid >> 5, lane = tid & 31;
    const int g = lane >> 2, tg = lane & 3;
    const int n0 = blockIdx.x * 64, o0 = blockIdx.y * 64;

    float sc[8][4];
#pragma unroll
    for (int nt = 0; nt < 8; nt++)
#pragma unroll
        for (int r = 0; r < 4; r++) sc[nt][r] = 0.f;

    for (int c0 = 0; c0 < CDIM; c0 += 64) {
#pragma unroll
        for (int i = 0; i < 8; i++) {
            int idx = i * 128 + tid, r = idx >> 4, c4 = (idx & 15) << 2;
            float4 v = *(const float4*)(W + (size_t)(o0 + r) * CDIM + c0 + c4);
            float* p = Ws + r * 68 + c4;
            p[0] = __uint_as_float(f2tf(v.x));
            p[1] = __uint_as_float(f2tf(v.y));
            p[2] = __uint_as_float(f2tf(v.z));
            p[3] = __uint_as_float(f2tf(v.w));
        }
#pragma unroll
        for (int i = 0; i < 8; i++) {
            int idx = i * 128 + tid, r = idx >> 4, c4 = (idx & 15) << 2;
            float4 v;
            float* p;
            if (MODE == 0) {
                v = *(const float4*)(X + (size_t)(c0 + r) * NSEQ + n0 + c4);
                p = Xs + r * 72 + c4;
            } else {
                v = *(const float4*)(X + (size_t)(n0 + r) * CDIM + c0 + c4);
                p = Xs + r * 68 + c4;
            }
            p[0] = __uint_as_float(f2tf(v.x));
            p[1] = __uint_as_float(f2tf(v.y));
            p[2] = __uint_as_float(f2tf(v.z));
            p[3] = __uint_as_float(f2tf(v.w));
        }
        __syncthreads();

#pragma unroll
        for (int ks = 0; ks < 8; ks++) {
            unsigned a0, a1, a2, a3;
            if (MODE == 0) {
                const float* xb = Xs + (8 * ks + tg) * 72 + 16 * w + g;
                a0 = FB(xb[0]); a1 = FB(xb[8]);
                const float* xb2 = xb + 4 * 72;
                a2 = FB(xb2[0]); a3 = FB(xb2[8]);
            } else {
                const float* xb = Xs + (16 * w + g) * 68 + 8 * ks;
                a0 = FB(xb[tg]); a1 = FB(xb[8 * 68 + tg]);
                a2 = FB(xb[tg + 4]); a3 = FB(xb[8 * 68 + tg + 4]);
            }
#pragma unroll
            for (int nt = 0; nt < 8; nt++) {
                const float* wb = Ws + (g + 8 * nt) * 68 + 8 * ks + tg;
                mma_tf32(sc[nt][0], sc[nt][1], sc[nt][2], sc[nt][3],
                         a0, a1, a2, a3, FB(wb[0]), FB(wb[4]));
            }
        }
        __syncthreads();
    }

    if (MODE == 0) {
        // direct transposed store: Y^T[n][o], tf32-rounded
        int n = n0 + 16 * w + g;
#pragma unroll
        for (int nt = 0; nt < 8; nt++) {
            int o = o0 + 8 * nt + 2 * tg;
            float b0 = __ldg(bias + o), b1 = __ldg(bias + o + 1);
            float2 v0, v1;
            v0.x = __uint_as_float(f2tf((sc[nt][0] + b0) * scale));
            v0.y = __uint_as_float(f2tf((sc[nt][1] + b1) * scale));
            v1.x = __uint_as_float(f2tf((sc[nt][2] + b0) * scale));
            v1.y = __uint_as_float(f2tf((sc[nt][3] + b1) * scale));
            *(float2*)(Y + (size_t)n * CDIM + o)       = v0;
            *(float2*)(Y + (size_t)(n + 8) * CDIM + o) = v1;
        }
    } else {
        // smem roundtrip -> natural [o][n] store
        float* Ys = smp;  // [n][o] stride 65 (4160 floats, fits in Ws area)
#pragma unroll
        for (int nt = 0; nt < 8; nt++) {
            int n = 16 * w + g, o = 8 * nt + 2 * tg;
            Ys[n * 65 + o]           = sc[nt][0];
            Ys[n * 65 + o + 1]       = sc[nt][1];
            Ys[(n + 8) * 65 + o]     = sc[nt][2];
            Ys[(n + 8) * 65 + o + 1] = sc[nt][3];
        }
        __syncthreads();
#pragma unroll
        for (int i = 0; i < 8; i++) {
            int idx = i * 128 + tid, o = idx & 63, n4 = (idx >> 6) << 2;
            float bb = __ldg(bias + o0 + o);
            float4 v;
            v.x = (Ys[(n4 + 0) * 65 + o] + bb) * scale;
            v.y = (Ys[(n4 + 1) * 65 + o] + bb) * scale;
            v.z = (Ys[(n4 + 2) * 65 + o] + bb) * scale;
            v.w = (Ys[(n4 + 3) * 65 + o] + bb) * scale;
            *(float4*)(Y + (size_t)(o0 + o) * NSEQ + n0 + n4) = v;
        }
    }
}

// ---------------------------------------------------------------------------
// Async-pipelined tf32 flash attention (log2-domain softmax).
// QT,KT,VT: [n][c] (tf32 pre-rounded; K pre-scaled by 0.125*log2e).
// AO: [n][c] output.  grid (64, 8 heads), 128 thr.
// Smem: Qs[q][c]@68 | Ks[k][c]@68 | Vts[k][d]@72  (53248 B dynamic).
// Pipeline: 2 barriers/tile; cp.async prefetch of K_{t+1} hidden behind
// softmax+PV, V_{t+1} hidden behind next S-phase.
// ---------------------------------------------------------------------------
__global__ __launch_bounds__(128) void attn_mma(
    const float* __restrict__ QT, const float* __restrict__ KT,
    const float* __restrict__ VT, float* __restrict__ AO)
{
    extern __shared__ float sm[];
    float* Qs  = sm;                 // stride 68
    float* Ks  = sm + 64 * 68;       // stride 68
    float* Vts = sm + 2 * 64 * 68;   // stride 72

    const int tid  = threadIdx.x;
    const int w    = tid >> 5, lane = tid & 31;
    const int g    = lane >> 2, tg = lane & 3;
    const int q0   = blockIdx.x * 64;
    const int hb   = blockIdx.y * 64;
    const unsigned FULL = 0xffffffffu;

    const uint32_t qs_u = (uint32_t)__cvta_generic_to_shared(Qs);
    const uint32_t ks_u = (uint32_t)__cvta_generic_to_shared(Ks);
    const uint32_t vs_u = (uint32_t)__cvta_generic_to_shared(Vts);

    // ---- prologue: Q + K_0 + V_0 via cp.async ----
#pragma unroll
    for (int i = 0; i < 8; i++) {
        int idx = i * 128 + tid, r = idx >> 4, c4 = (idx & 15) << 2;
        cp16(qs_u + (r * 68 + c4) * 4, QT + (size_t)(q0 + r) * CDIM + hb + c4);
        cp16(ks_u + (r * 68 + c4) * 4, KT + (size_t)r * CDIM + hb + c4);
        cp16(vs_u + (r * 72 + c4) * 4, VT + (size_t)r * CDIM + hb + c4);
    }
    cp_commit();
    cp_wait0();
    __syncthreads();

    float m0 = -1e30f, m1 = -1e30f, l0 = 0.f, l1 = 0.f;
    float oa[4][2][4];
#pragma unroll
    for (int mt = 0; mt < 4; mt++)
#pragma unroll
        for (int np = 0; np < 2; np++)
#pragma unroll
            for (int r = 0; r < 4; r++) oa[mt][np][r] = 0.f;

    const float* qb = Qs + (16 * w + g) * 68;

    for (int it = 0; it < 64; it++) {
        const int t0 = it * 64;

        // ---- S = Q K^T ----
        float sc[8][4];
#pragma unroll
        for (int nt = 0; nt < 8; nt++)
#pragma unroll
            for (int r = 0; r < 4; r++) sc[nt][r] = 0.f;

#pragma unroll
        for (int ks = 0; ks < 8; ks++) {
            unsigned a0 = FB(qb[8 * ks + tg]);
            unsigned a1 = FB(qb[8 * 68 + 8 * ks + tg]);
            unsigned a2 = FB(qb[8 * ks + tg + 4]);
            unsigned a3 = FB(qb[8 * 68 + 8 * ks + tg + 4]);
#pragma unroll
            for (int nt = 0; nt < 8; nt++) {
                const float* kb = Ks + (g + 8 * nt) * 68 + 8 * ks + tg;
                mma_tf32(sc[nt][0], sc[nt][1], sc[nt][2], sc[nt][3],
                         a0, a1, a2, a3, FB(kb[0]), FB(kb[4]));
            }
        }

        cp_wait0();        // V_t copies complete (no-op at it=0)
        __syncthreads();   // Ks free; Vts data published to all warps

        if (it < 63) {     // prefetch K_{t+1} (hidden behind softmax + PV)
            const float* kn = KT + (size_t)(t0 + 64) * CDIM + hb;
#pragma unroll
            for (int i = 0; i < 8; i++) {
                int idx = i * 128 + tid, r = idx >> 4, c4 = (idx & 15) << 2;
                cp16(ks_u + (r * 68 + c4) * 4, kn + (size_t)r * CDIM + c4);
            }
            cp_commit();
        }

        // ---- online softmax (log2 domain; scores already * log2e) ----
        float mx0 = -1e30f, mx1 = -1e30f;
#pragma unroll
        for (int nt = 0; nt < 8; nt++) {
            mx0 = fmaxf(mx0, fmaxf(sc[nt][0], sc[nt][1]));
            mx1 = fmaxf(mx1, fmaxf(sc[nt][2], sc[nt][3]));
        }
        mx0 = fmaxf(mx0, __shfl_xor_sync(FULL, mx0, 1));
        mx0 = fmaxf(mx0, __shfl_xor_sync(FULL, mx0, 2));
        mx1 = fmaxf(mx1, __shfl_xor_sync(FULL, mx1, 1));
        mx1 = fmaxf(mx1, __shfl_xor_sync(FULL, mx1, 2));

        float nm0 = fmaxf(m0, mx0), nm1 = fmaxf(m1, mx1);
        float al0 = ex2f(m0 - nm0), al1 = ex2f(m1 - nm1);
        float s0 = 0.f, s1 = 0.f;
#pragma unroll
        for (int nt = 0; nt < 8; nt++) {
            sc[nt][0] = ex2f(sc[nt][0] - nm0);
            sc[nt][1] = ex2f(sc[nt][1] - nm0);
            sc[nt][2] = ex2f(sc[nt][2] - nm1);
            sc[nt][3] = ex2f(sc[nt][3] - nm1);
            s0 += sc[nt][0] + sc[nt][1];
            s1 += sc[nt][2] + sc[nt][3];
        }
        s0 += __shfl_xor_sync(FULL, s0, 1);
        s0 += __shfl_xor_sync(FULL, s0, 2);
        s1 += __shfl_xor_sync(FULL, s1, 1);
        s1 += __shfl_xor_sync(FULL, s1, 2);
        l0 = l0 * al0 + s0;
        l1 = l1 * al1 + s1;
        m0 = nm0; m1 = nm1;

        // ---- rescale O accumulators ----
        float av00 = __shfl_sync(FULL, al0, (2 * tg) << 2);
        float av01 = __shfl_sync(FULL, al0, (2 * tg + 1) << 2);
        float av10 = __shfl_sync(FULL, al1, (2 * tg) << 2);
        float av11 = __shfl_sync(FULL, al1, (2 * tg + 1) << 2);
#pragma unroll
        for (int mt = 0; mt < 4; mt++) {
            oa[mt][0][0] *= av00; oa[mt][0][1] *= av01;
            oa[mt][0][2] *= av00; oa[mt][0][3] *= av01;
            oa[mt][1][0] *= av10; oa[mt][1][1] *= av11;
            oa[mt][1][2] *= av10; oa[mt][1][3] *= av11;
        }

        // ---- O^T += V^T P^T  (A-frags from Vts[k][d], stride 72) ----
        const int s0l = (g << 2) | (tg >> 1);
        const int s1l = s0l + 2;
#pragma unroll
        for (int ks = 0; ks < 8; ks++) {
            float y0 = __shfl_sync(FULL, sc[ks][0], s0l);
            float y1 = __shfl_sync(FULL, sc[ks][1], s0l);
            float y2 = __shfl_sync(FULL, sc[ks][0], s1l);
            float y3 = __shfl_sync(FULL, sc[ks][1], s1l);
            unsigned b00 = f2tf((tg & 1) ? y1 : y0);
            unsigned b01 = f2tf((tg & 1) ? y3 : y2);
            float z0 = __shfl_sync(FULL, sc[ks][2], s0l);
            float z1 = __shfl_sync(FULL, sc[ks][3], s0l);
            float z2 = __shfl_sync(FULL, sc[ks][2], s1l);
            float z3 = __shfl_sync(FULL, sc[ks][3], s1l);
            unsigned b10 = f2tf((tg & 1) ? z1 : z0);
            unsigned b11 = f2tf((tg & 1) ? z3 : z2);

            const float* va = Vts + (8 * ks + tg) * 72;
            const float* vb = Vts + (8 * ks + tg + 4) * 72;
#pragma unroll
            for (int mt = 0; mt < 4; mt++) {
                unsigned a0 = FB(va[16 * mt + g]);
                unsigned a1 = FB(va[16 * mt + g + 8]);
                unsigned a2 = FB(vb[16 * mt + g]);
                unsigned a3 = FB(vb[16 * mt + g + 8]);
                mma_tf32(oa[mt][0][0], oa[mt][0][1], oa[mt][0][2], oa[mt][0][3],
                         a0, a1, a2, a3, b00, b01);
                mma_tf32(oa[mt][1][0], oa[mt][1][1], oa[mt][1][2], oa[mt][1][3],
                         a0, a1, a2, a3, b10, b11);
            }
        }

        cp_wait0();        // K_{t+1} copies complete
        __syncthreads();   // Vts free; Ks data published

        if (it < 63) {     // prefetch V_{t+1} (hidden behind next S-phase)
            const float* vn = VT + (size_t)(t0 + 64) * CDIM + hb;
#pragma unroll
            for (int i = 0; i < 8; i++) {
                int idx = i * 128 + tid, r = idx >> 4, c4 = (idx & 15) << 2;
                cp16(vs_u + (r * 72 + c4) * 4, vn + (size_t)r * CDIM + c4);
            }
            cp_commit();
        }
    }

    // ---- normalize, store to AO[n][c] ([q][d]) ----
    float inv0 = 1.f / l0, inv1 = 1.f / l1;
    float n00 = __shfl_sync(FULL, inv0, (2 * tg) << 2);
    float n01 = __shfl_sync(FULL, inv0, (2 * tg + 1) << 2);
    float n10 = __shfl_sync(FULL, inv1, (2 * tg) << 2);
    float n11 = __shfl_sync(FULL, inv1, (2 * tg + 1) << 2);

#pragma unroll
    for (int mt = 0; mt < 4; mt++) {
#pragma unroll
        for (int np = 0; np < 2; np++) {
            float sa = np ? n10 : n00;
            float sb = np ? n11 : n01;
            int qa = q0 + 16 * w + 8 * np + 2 * tg;
            int d  = hb + 16 * mt + g;
            AO[(size_t)qa * CDIM + d]           = oa[mt][np][0] * sa;
            AO[(size_t)(qa + 1) * CDIM + d]     = oa[mt][np][1] * sb;
            AO[(size_t)qa * CDIM + d + 8]       = oa[mt][np][2] * sa;
            AO[(size_t)(qa + 1) * CDIM + d + 8] = oa[mt][np][3] * sb;
        }
    }
}

// ---------------------------------------------------------------------------
extern "C" void kernel_launch(void* const* d_in, const int* in_sizes, int n_in,
                              void* d_out, int out_size)
{
    const float* x   = (const float*)d_in[0];
    const float* q_w = (const float*)d_in[1];
    const float* q_b = (const float*)d_in[2];
    const float* k_w = (const float*)d_in[3];
    const float* k_b = (const float*)d_in[4];
    const float* v_w = (const float*)d_in[5];
    const float* v_b = (const float*)d_in[6];
    const float* o_w = (const float*)d_in[7];
    const float* o_b = (const float*)d_in[8];
    float* out = (float*)d_out;

    float *gq, *gk, *gv, *gao;
    cudaGetSymbolAddress((void**)&gq,  g_q);
    cudaGetSymbolAddress((void**)&gk,  g_k);
    cudaGetSymbolAddress((void**)&gv,  g_v);
    cudaGetSymbolAddress((void**)&gao, g_ao);

    // HEAD_DIM^-0.5 * log2(e): K projection pre-scales logits into log2 domain
    const float kSCALE = 0.125f * 1.4426950408889634f;

    dim3 pgrid(NSEQ / 64, CDIM / 64);
    gemm_tf32<0><<<pgrid, 128>>>(q_w, q_b, x, gq, 1.0f);
    gemm_tf32<0><<<pgrid, 128>>>(k_w, k_b, x, gk, kSCALE);
    gemm_tf32<0><<<pgrid, 128>>>(v_w, v_b, x, gv, 1.0f);

    const int ATTN_SMEM = (2 * 64 * 68 + 64 * 72) * 4;  // 53248 B
    cudaFuncSetAttribute(attn_mma, cudaFuncAttributeMaxDynamicSharedMemorySize,
                         ATTN_SMEM);
    dim3 agrid(NSEQ / 64, 8);
    attn_mma<<<agrid, 128, ATTN_SMEM>>>(gq, gk, gv, gao);

    gemm_tf32<1><<<pgrid, 128>>>(o_w, o_b, gao, out, 1.0f);
}

// round 10
// speedup vs baseline: 3.9186x; 1.0117x over previous
#include <cuda_runtime.h>
#include <cstdint>

#define NSEQ 4096
#define CDIM 512

// Scratch (allocation-free rule: __device__ globals)
__device__ float g_q[CDIM * NSEQ];   // Q^T [n][c], tf32-rounded
__device__ float g_k[CDIM * NSEQ];   // K^T [n][c], scaled by 0.125*log2e, tf32-rounded
__device__ float g_v[CDIM * NSEQ];   // V^T [n][c], tf32-rounded
__device__ float g_ao[CDIM * NSEQ];  // attention out [n][c]

__device__ __forceinline__ unsigned f2tf(float f) {
    unsigned u; asm("cvt.rna.tf32.f32 %0, %1;" : "=r"(u) : "f"(f)); return u;
}
__device__ __forceinline__ float ex2f(float x) {
    float y; asm("ex2.approx.f32 %0, %1;" : "=f"(y) : "f"(x)); return y;
}
__device__ __forceinline__ void cp16(uint32_t dst, const float* src) {
    asm volatile("cp.async.cg.shared.global [%0], [%1], 16;" :: "r"(dst), "l"(src));
}
__device__ __forceinline__ void cp_commit() { asm volatile("cp.async.commit_group;"); }
__device__ __forceinline__ void cp_wait0()  { asm volatile("cp.async.wait_group 0;" ::: "memory"); }

__device__ __forceinline__ void mma_tf32(
    float& c0, float& c1, float& c2, float& c3,
    unsigned a0, unsigned a1, unsigned a2, unsigned a3,
    unsigned b0, unsigned b1)
{
    asm volatile(
        "mma.sync.aligned.m16n8k8.row.col.f32.tf32.tf32.f32 "
        "{%0,%1,%2,%3},{%4,%5,%6,%7},{%8,%9},{%0,%1,%2,%3};"
        : "+f"(c0), "+f"(c1), "+f"(c2), "+f"(c3)
        : "r"(a0), "r"(a1), "r"(a2), "r"(a3), "r"(b0), "r"(b1));
}
#define FB(x) __float_as_uint(x)

// ---------------------------------------------------------------------------
// Fused Q/K/V projection (tf32 MMA).  X[c][n] global, W_p[o][c], bias_p[o].
// Outputs Y_p^T[n][o], tf32-rounded, scaled (scale folded per-projection).
// Smem: 3 W tiles (resident) + 1 X tile; X loaded & converted ONCE per chunk.
// ---------------------------------------------------------------------------
__global__ __launch_bounds__(128) void qkv_proj(
    const float* __restrict__ X,
    const float* __restrict__ Wq, const float* __restrict__ Bq,
    const float* __restrict__ Wk, const float* __restrict__ Bk,
    const float* __restrict__ Wv, const float* __restrict__ Bv,
    float* __restrict__ Yq, float* __restrict__ Yk, float* __restrict__ Yv,
    float scale_k)
{
    extern __shared__ float smp[];
    float* Ws0 = smp;                  // [o][c] stride 68 (Q weights)
    float* Ws1 = smp + 64 * 68;        // K weights
    float* Ws2 = smp + 2 * 64 * 68;    // V weights
    float* Xs  = smp + 3 * 64 * 68;    // [c][n] stride 72

    const int tid = threadIdx.x, w = tid >> 5, lane = tid & 31;
    const int g = lane >> 2, tg = lane & 3;
    const int n0 = blockIdx.x * 64, o0 = blockIdx.y * 64;

    const float* Wp[3] = {Wq, Wk, Wv};
    float* Wsp[3] = {Ws0, Ws1, Ws2};

    float sc[3][8][4];
#pragma unroll
    for (int p = 0; p < 3; p++)
#pragma unroll
        for (int nt = 0; nt < 8; nt++)
#pragma unroll
            for (int r = 0; r < 4; r++) sc[p][nt][r] = 0.f;

    for (int c0 = 0; c0 < CDIM; c0 += 64) {
#pragma unroll
        for (int p = 0; p < 3; p++) {
#pragma unroll
            for (int i = 0; i < 8; i++) {
                int idx = i * 128 + tid, r = idx >> 4, c4 = (idx & 15) << 2;
                float4 v = *(const float4*)(Wp[p] + (size_t)(o0 + r) * CDIM + c0 + c4);
                float* q = Wsp[p] + r * 68 + c4;
                q[0] = __uint_as_float(f2tf(v.x));
                q[1] = __uint_as_float(f2tf(v.y));
                q[2] = __uint_as_float(f2tf(v.z));
                q[3] = __uint_as_float(f2tf(v.w));
            }
        }
#pragma unroll
        for (int i = 0; i < 8; i++) {
            int idx = i * 128 + tid, r = idx >> 4, c4 = (idx & 15) << 2;
            float4 v = *(const float4*)(X + (size_t)(c0 + r) * NSEQ + n0 + c4);
            float* q = Xs + r * 72 + c4;
            q[0] = __uint_as_float(f2tf(v.x));
            q[1] = __uint_as_float(f2tf(v.y));
            q[2] = __uint_as_float(f2tf(v.z));
            q[3] = __uint_as_float(f2tf(v.w));
        }
        __syncthreads();

#pragma unroll
        for (int ks = 0; ks < 8; ks++) {
            const float* xb = Xs + (8 * ks + tg) * 72 + 16 * w + g;
            unsigned a0 = FB(xb[0]), a1 = FB(xb[8]);
            const float* xb2 = xb + 4 * 72;
            unsigned a2 = FB(xb2[0]), a3 = FB(xb2[8]);
#pragma unroll
            for (int p = 0; p < 3; p++) {
#pragma unroll
                for (int nt = 0; nt < 8; nt++) {
                    const float* wb = Wsp[p] + (g + 8 * nt) * 68 + 8 * ks + tg;
                    mma_tf32(sc[p][nt][0], sc[p][nt][1], sc[p][nt][2], sc[p][nt][3],
                             a0, a1, a2, a3, FB(wb[0]), FB(wb[4]));
                }
            }
        }
        __syncthreads();
    }

    const float* Bp[3] = {Bq, Bk, Bv};
    float* Yp[3] = {Yq, Yk, Yv};
    int n = n0 + 16 * w + g;
#pragma unroll
    for (int p = 0; p < 3; p++) {
        float scl = (p == 1) ? scale_k : 1.0f;
#pragma unroll
        for (int nt = 0; nt < 8; nt++) {
            int o = o0 + 8 * nt + 2 * tg;
            float b0 = __ldg(Bp[p] + o), b1 = __ldg(Bp[p] + o + 1);
            float2 v0, v1;
            v0.x = __uint_as_float(f2tf((sc[p][nt][0] + b0) * scl));
            v0.y = __uint_as_float(f2tf((sc[p][nt][1] + b1) * scl));
            v1.x = __uint_as_float(f2tf((sc[p][nt][2] + b0) * scl));
            v1.y = __uint_as_float(f2tf((sc[p][nt][3] + b1) * scl));
            *(float2*)(Yp[p] + (size_t)n * CDIM + o)       = v0;
            *(float2*)(Yp[p] + (size_t)(n + 8) * CDIM + o) = v1;
        }
    }
}

// ---------------------------------------------------------------------------
// Final O projection (tf32 MMA).  X[n][c] global; output Y[o][n] fp32.
// ---------------------------------------------------------------------------
__global__ __launch_bounds__(128) void gemm_oproj(
    const float* __restrict__ W, const float* __restrict__ bias,
    const float* __restrict__ X, float* __restrict__ Y)
{
    __shared__ float smp[64 * 68 + 64 * 68];
    float* Ws = smp;             // [o][c] stride 68
    float* Xs = smp + 64 * 68;   // [n][c] stride 68

    const int tid = threadIdx.x, w = tid >> 5, lane = tid & 31;
    const int g = lane >> 2, tg = lane & 3;
    const int n0 = blockIdx.x * 64, o0 = blockIdx.y * 64;

    float sc[8][4];
#pragma unroll
    for (int nt = 0; nt < 8; nt++)
#pragma unroll
        for (int r = 0; r < 4; r++) sc[nt][r] = 0.f;

    for (int c0 = 0; c0 < CDIM; c0 += 64) {
#pragma unroll
        for (int i = 0; i < 8; i++) {
            int idx = i * 128 + tid, r = idx >> 4, c4 = (idx & 15) << 2;
            float4 v = *(const float4*)(W + (size_t)(o0 + r) * CDIM + c0 + c4);
            float* p = Ws + r * 68 + c4;
            p[0] = __uint_as_float(f2tf(v.x));
            p[1] = __uint_as_float(f2tf(v.y));
            p[2] = __uint_as_float(f2tf(v.z));
            p[3] = __uint_as_float(f2tf(v.w));
        }
#pragma unroll
        for (int i = 0; i < 8; i++) {
            int idx = i * 128 + tid, r = idx >> 4, c4 = (idx & 15) << 2;
            float4 v = *(const float4*)(X + (size_t)(n0 + r) * CDIM + c0 + c4);
            float* p = Xs + r * 68 + c4;
            p[0] = __uint_as_float(f2tf(v.x));
            p[1] = __uint_as_float(f2tf(v.y));
            p[2] = __uint_as_float(f2tf(v.z));
            p[3] = __uint_as_float(f2tf(v.w));
        }
        __syncthreads();

#pragma unroll
        for (int ks = 0; ks < 8; ks++) {
            const float* xb = Xs + (16 * w + g) * 68 + 8 * ks;
            unsigned a0 = FB(xb[tg]),     a1 = FB(xb[8 * 68 + tg]);
            unsigned a2 = FB(xb[tg + 4]), a3 = FB(xb[8 * 68 + tg + 4]);
#pragma unroll
            for (int nt = 0; nt < 8; nt++) {
                const float* wb = Ws + (g + 8 * nt) * 68 + 8 * ks + tg;
                mma_tf32(sc[nt][0], sc[nt][1], sc[nt][2], sc[nt][3],
                         a0, a1, a2, a3, FB(wb[0]), FB(wb[4]));
            }
        }
        __syncthreads();
    }

    // smem roundtrip -> natural [o][n] store
    float* Ys = smp;  // [n][o] stride 65
#pragma unroll
    for (int nt = 0; nt < 8; nt++) {
        int n = 16 * w + g, o = 8 * nt + 2 * tg;
        Ys[n * 65 + o]           = sc[nt][0];
        Ys[n * 65 + o + 1]       = sc[nt][1];
        Ys[(n + 8) * 65 + o]     = sc[nt][2];
        Ys[(n + 8) * 65 + o + 1] = sc[nt][3];
    }
    __syncthreads();
#pragma unroll
    for (int i = 0; i < 8; i++) {
        int idx = i * 128 + tid, o = idx & 63, n4 = (idx >> 6) << 2;
        float bb = __ldg(bias + o0 + o);
        float4 v;
        v.x = Ys[(n4 + 0) * 65 + o] + bb;
        v.y = Ys[(n4 + 1) * 65 + o] + bb;
        v.z = Ys[(n4 + 2) * 65 + o] + bb;
        v.w = Ys[(n4 + 3) * 65 + o] + bb;
        *(float4*)(Y + (size_t)(o0 + o) * NSEQ + n0 + n4) = v;
    }
}

// ---------------------------------------------------------------------------
// Async-pipelined tf32 flash attention (log2-domain softmax).
// QT,KT,VT: [n][c] (tf32 pre-rounded; K pre-scaled by 0.125*log2e).
// AO: [n][c] output.  grid (64, 8 heads), 128 thr.
// __launch_bounds__(128, 4): cap regs at 128 -> 4 blocks/SM -> single wave
// (592 capacity >= 512 grid) and 16 warps/SM for latency hiding.
// ---------------------------------------------------------------------------
__global__ __launch_bounds__(128, 4) void attn_mma(
    const float* __restrict__ QT, const float* __restrict__ KT,
    const float* __restrict__ VT, float* __restrict__ AO)
{
    extern __shared__ float sm[];
    float* Qs  = sm;                 // stride 68
    float* Ks  = sm + 64 * 68;       // stride 68
    float* Vts = sm + 2 * 64 * 68;   // stride 72

    const int tid  = threadIdx.x;
    const int w    = tid >> 5, lane = tid & 31;
    const int g    = lane >> 2, tg = lane & 3;
    const int q0   = blockIdx.x * 64;
    const int hb   = blockIdx.y * 64;
    const unsigned FULL = 0xffffffffu;

    const uint32_t qs_u = (uint32_t)__cvta_generic_to_shared(Qs);
    const uint32_t ks_u = (uint32_t)__cvta_generic_to_shared(Ks);
    const uint32_t vs_u = (uint32_t)__cvta_generic_to_shared(Vts);

    // ---- prologue: Q + K_0 + V_0 via cp.async ----
#pragma unroll
    for (int i = 0; i < 8; i++) {
        int idx = i * 128 + tid, r = idx >> 4, c4 = (idx & 15) << 2;
        cp16(qs_u + (r * 68 + c4) * 4, QT + (size_t)(q0 + r) * CDIM + hb + c4);
        cp16(ks_u + (r * 68 + c4) * 4, KT + (size_t)r * CDIM + hb + c4);
        cp16(vs_u + (r * 72 + c4) * 4, VT + (size_t)r * CDIM + hb + c4);
    }
    cp_commit();
    cp_wait0();
    __syncthreads();

    float m0 = -1e30f, m1 = -1e30f, l0 = 0.f, l1 = 0.f;
    float oa[4][2][4];
#pragma unroll
    for (int mt = 0; mt < 4; mt++)
#pragma unroll
        for (int np = 0; np < 2; np++)
#pragma unroll
            for (int r = 0; r < 4; r++) oa[mt][np][r] = 0.f;

    const float* qb = Qs + (16 * w + g) * 68;

    for (int it = 0; it < 64; it++) {
        const int t0 = it * 64;

        // ---- S = Q K^T ----
        float sc[8][4];
#pragma unroll
        for (int nt = 0; nt < 8; nt++)
#pragma unroll
            for (int r = 0; r < 4; r++) sc[nt][r] = 0.f;

#pragma unroll
        for (int ks = 0; ks < 8; ks++) {
            unsigned a0 = FB(qb[8 * ks + tg]);
            unsigned a1 = FB(qb[8 * 68 + 8 * ks + tg]);
            unsigned a2 = FB(qb[8 * ks + tg + 4]);
            unsigned a3 = FB(qb[8 * 68 + 8 * ks + tg + 4]);
#pragma unroll
            for (int nt = 0; nt < 8; nt++) {
                const float* kb = Ks + (g + 8 * nt) * 68 + 8 * ks + tg;
                mma_tf32(sc[nt][0], sc[nt][1], sc[nt][2], sc[nt][3],
                         a0, a1, a2, a3, FB(kb[0]), FB(kb[4]));
            }
        }

        cp_wait0();        // V_t copies complete (no-op at it=0)
        __syncthreads();   // Ks free; Vts data published to all warps

        if (it < 63) {     // prefetch K_{t+1} (hidden behind softmax + PV)
            const float* kn = KT + (size_t)(t0 + 64) * CDIM + hb;
#pragma unroll
            for (int i = 0; i < 8; i++) {
                int idx = i * 128 + tid, r = idx >> 4, c4 = (idx & 15) << 2;
                cp16(ks_u + (r * 68 + c4) * 4, kn + (size_t)r * CDIM + c4);
            }
            cp_commit();
        }

        // ---- online softmax (log2 domain; scores already * log2e) ----
        float mx0 = -1e30f, mx1 = -1e30f;
#pragma unroll
        for (int nt = 0; nt < 8; nt++) {
            mx0 = fmaxf(mx0, fmaxf(sc[nt][0], sc[nt][1]));
            mx1 = fmaxf(mx1, fmaxf(sc[nt][2], sc[nt][3]));
        }
        mx0 = fmaxf(mx0, __shfl_xor_sync(FULL, mx0, 1));
        mx0 = fmaxf(mx0, __shfl_xor_sync(FULL, mx0, 2));
        mx1 = fmaxf(mx1, __shfl_xor_sync(FULL, mx1, 1));
        mx1 = fmaxf(mx1, __shfl_xor_sync(FULL, mx1, 2));

        float nm0 = fmaxf(m0, mx0), nm1 = fmaxf(m1, mx1);
        float al0 = ex2f(m0 - nm0), al1 = ex2f(m1 - nm1);
        float s0 = 0.f, s1 = 0.f;
#pragma unroll
        for (int nt = 0; nt < 8; nt++) {
            sc[nt][0] = ex2f(sc[nt][0] - nm0);
            sc[nt][1] = ex2f(sc[nt][1] - nm0);
            sc[nt][2] = ex2f(sc[nt][2] - nm1);
            sc[nt][3] = ex2f(sc[nt][3] - nm1);
            s0 += sc[nt][0] + sc[nt][1];
            s1 += sc[nt][2] + sc[nt][3];
        }
        s0 += __shfl_xor_sync(FULL, s0, 1);
        s0 += __shfl_xor_sync(FULL, s0, 2);
        s1 += __shfl_xor_sync(FULL, s1, 1);
        s1 += __shfl_xor_sync(FULL, s1, 2);
        l0 = l0 * al0 + s0;
        l1 = l1 * al1 + s1;
        m0 = nm0; m1 = nm1;

        // ---- rescale O accumulators ----
        float av00 = __shfl_sync(FULL, al0, (2 * tg) << 2);
        float av01 = __shfl_sync(FULL, al0, (2 * tg + 1) << 2);
        float av10 = __shfl_sync(FULL, al1, (2 * tg) << 2);
        float av11 = __shfl_sync(FULL, al1, (2 * tg + 1) << 2);
#pragma unroll
        for (int mt = 0; mt < 4; mt++) {
            oa[mt][0][0] *= av00; oa[mt][0][1] *= av01;
            oa[mt][0][2] *= av00; oa[mt][0][3] *= av01;
            oa[mt][1][0] *= av10; oa[mt][1][1] *= av11;
            oa[mt][1][2] *= av10; oa[mt][1][3] *= av11;
        }

        // ---- O^T += V^T P^T  (A-frags from Vts[k][d], stride 72) ----
        const int s0l = (g << 2) | (tg >> 1);
        const int s1l = s0l + 2;
#pragma unroll
        for (int ks = 0; ks < 8; ks++) {
            float y0 = __shfl_sync(FULL, sc[ks][0], s0l);
            float y1 = __shfl_sync(FULL, sc[ks][1], s0l);
            float y2 = __shfl_sync(FULL, sc[ks][0], s1l);
            float y3 = __shfl_sync(FULL, sc[ks][1], s1l);
            unsigned b00 = f2tf((tg & 1) ? y1 : y0);
            unsigned b01 = f2tf((tg & 1) ? y3 : y2);
            float z0 = __shfl_sync(FULL, sc[ks][2], s0l);
            float z1 = __shfl_sync(FULL, sc[ks][3], s0l);
            float z2 = __shfl_sync(FULL, sc[ks][2], s1l);
            float z3 = __shfl_sync(FULL, sc[ks][3], s1l);
            unsigned b10 = f2tf((tg & 1) ? z1 : z0);
            unsigned b11 = f2tf((tg & 1) ? z3 : z2);

            const float* va = Vts + (8 * ks + tg) * 72;
            const float* vb = Vts + (8 * ks + tg + 4) * 72;
#pragma unroll
            for (int mt = 0; mt < 4; mt++) {
                unsigned a0 = FB(va[16 * mt + g]);
                unsigned a1 = FB(va[16 * mt + g + 8]);
                unsigned a2 = FB(vb[16 * mt + g]);
                unsigned a3 = FB(vb[16 * mt + g + 8]);
                mma_tf32(oa[mt][0][0], oa[mt][0][1], oa[mt][0][2], oa[mt][0][3],
                         a0, a1, a2, a3, b00, b01);
                mma_tf32(oa[mt][1][0], oa[mt][1][1], oa[mt][1][2], oa[mt][1][3],
                         a0, a1, a2, a3, b10, b11);
            }
        }

        cp_wait0();        // K_{t+1} copies complete
        __syncthreads();   // Vts free; Ks data published

        if (it < 63) {     // prefetch V_{t+1} (hidden behind next S-phase)
            const float* vn = VT + (size_t)(t0 + 64) * CDIM + hb;
#pragma unroll
            for (int i = 0; i < 8; i++) {
                int idx = i * 128 + tid, r = idx >> 4, c4 = (idx & 15) << 2;
                cp16(vs_u + (r * 72 + c4) * 4, vn + (size_t)r * CDIM + c4);
            }
            cp_commit();
        }
    }

    // ---- normalize, store to AO[n][c] ([q][d]) ----
    float inv0 = 1.f / l0, inv1 = 1.f / l1;
    float n00 = __shfl_sync(FULL, inv0, (2 * tg) << 2);
    float n01 = __shfl_sync(FULL, inv0, (2 * tg + 1) << 2);
    float n10 = __shfl_sync(FULL, inv1, (2 * tg) << 2);
    float n11 = __shfl_sync(FULL, inv1, (2 * tg + 1) << 2);

#pragma unroll
    for (int mt = 0; mt < 4; mt++) {
#pragma unroll
        for (int np = 0; np < 2; np++) {
            float sa = np ? n10 : n00;
            float sb = np ? n11 : n01;
            int qa = q0 + 16 * w + 8 * np + 2 * tg;
            int d  = hb + 16 * mt + g;
            AO[(size_t)qa * CDIM + d]           = oa[mt][np][0] * sa;
            AO[(size_t)(qa + 1) * CDIM + d]     = oa[mt][np][1] * sb;
            AO[(size_t)qa * CDIM + d + 8]       = oa[mt][np][2] * sa;
            AO[(size_t)(qa + 1) * CDIM + d + 8] = oa[mt][np][3] * sb;
        }
    }
}

// ---------------------------------------------------------------------------
extern "C" void kernel_launch(void* const* d_in, const int* in_sizes, int n_in,
                              void* d_out, int out_size)
{
    const float* x   = (const float*)d_in[0];
    const float* q_w = (const float*)d_in[1];
    const float* q_b = (const float*)d_in[2];
    const float* k_w = (const float*)d_in[3];
    const float* k_b = (const float*)d_in[4];
    const float* v_w = (const float*)d_in[5];
    const float* v_b = (const float*)d_in[6];
    const float* o_w = (const float*)d_in[7];
    const float* o_b = (const float*)d_in[8];
    float* out = (float*)d_out;

    float *gq, *gk, *gv, *gao;
    cudaGetSymbolAddress((void**)&gq,  g_q);
    cudaGetSymbolAddress((void**)&gk,  g_k);
    cudaGetSymbolAddress((void**)&gv,  g_v);
    cudaGetSymbolAddress((void**)&gao, g_ao);

    // HEAD_DIM^-0.5 * log2(e): K projection pre-scales logits into log2 domain
    const float kSCALE = 0.125f * 1.4426950408889634f;

    const int QKV_SMEM = (3 * 64 * 68 + 64 * 72) * 4;   // 70656 B
    cudaFuncSetAttribute(qkv_proj, cudaFuncAttributeMaxDynamicSharedMemorySize,
                         QKV_SMEM);
    dim3 pgrid(NSEQ / 64, CDIM / 64);
    qkv_proj<<<pgrid, 128, QKV_SMEM>>>(x, q_w, q_b, k_w, k_b, v_w, v_b,
                                       gq, gk, gv, kSCALE);

    const int ATTN_SMEM = (2 * 64 * 68 + 64 * 72) * 4;  // 53248 B
    cudaFuncSetAttribute(attn_mma, cudaFuncAttributeMaxDynamicSharedMemorySize,
                         ATTN_SMEM);
    dim3 agrid(NSEQ / 64, 8);
    attn_mma<<<agrid, 128, ATTN_SMEM>>>(gq, gk, gv, gao);

    gemm_oproj<<<pgrid, 128>>>(o_w, o_b, gao, out);
}

// round 11
// speedup vs baseline: 5.9211x; 1.5110x over previous
#include <cuda_runtime.h>
#include <cuda_fp16.h>
#include <cstdint>

#define NSEQ 4096
#define CDIM 512

// Scratch (allocation-free rule: __device__ globals)
__device__ __half g_q[CDIM * NSEQ];   // Q^T [n][c] fp16
__device__ __half g_k[CDIM * NSEQ];   // K^T [n][c] fp16, scaled by 0.125*log2e
__device__ __half g_v[CDIM * NSEQ];   // V   [c][n] fp16 (natural)
__device__ float  g_ao[CDIM * NSEQ];  // attention out [n][c] fp32

__device__ __forceinline__ unsigned f2tf(float f) {
    unsigned u; asm("cvt.rna.tf32.f32 %0, %1;" : "=r"(u) : "f"(f)); return u;
}
__device__ __forceinline__ float ex2f(float x) {
    float y; asm("ex2.approx.f32 %0, %1;" : "=f"(y) : "f"(x)); return y;
}
__device__ __forceinline__ void cp16(uint32_t dst, const void* src) {
    asm volatile("cp.async.cg.shared.global [%0], [%1], 16;" :: "r"(dst), "l"(src));
}
__device__ __forceinline__ void cp_commit() { asm volatile("cp.async.commit_group;"); }
__device__ __forceinline__ void cp_wait0()  { asm volatile("cp.async.wait_group 0;" ::: "memory"); }

__device__ __forceinline__ void mma_tf32(
    float& c0, float& c1, float& c2, float& c3,
    unsigned a0, unsigned a1, unsigned a2, unsigned a3,
    unsigned b0, unsigned b1)
{
    asm volatile(
        "mma.sync.aligned.m16n8k8.row.col.f32.tf32.tf32.f32 "
        "{%0,%1,%2,%3},{%4,%5,%6,%7},{%8,%9},{%0,%1,%2,%3};"
        : "+f"(c0), "+f"(c1), "+f"(c2), "+f"(c3)
        : "r"(a0), "r"(a1), "r"(a2), "r"(a3), "r"(b0), "r"(b1));
}
__device__ __forceinline__ void mma_f16(
    float& c0, float& c1, float& c2, float& c3,
    unsigned a0, unsigned a1, unsigned a2, unsigned a3,
    unsigned b0, unsigned b1)
{
    asm volatile(
        "mma.sync.aligned.m16n8k16.row.col.f32.f16.f16.f32 "
        "{%0,%1,%2,%3},{%4,%5,%6,%7},{%8,%9},{%0,%1,%2,%3};"
        : "+f"(c0), "+f"(c1), "+f"(c2), "+f"(c3)
        : "r"(a0), "r"(a1), "r"(a2), "r"(a3), "r"(b0), "r"(b1));
}
#define FB(x) __float_as_uint(x)
#define H2U(h) (*(const unsigned*)&(h))

// ---------------------------------------------------------------------------
// Q/K projection (tf32 MMA compute).  X[c][n] fp32, W[o][c], bias[o].
// Output Y^T[n][o] fp16, scaled.
// ---------------------------------------------------------------------------
__global__ __launch_bounds__(128) void gemm_qk(
    const float* __restrict__ W, const float* __restrict__ bias,
    const float* __restrict__ X, __half* __restrict__ Yh, float scale)
{
    __shared__ float smp[64 * 68 + 64 * 72];
    float* Ws = smp;             // [o][c] stride 68
    float* Xs = smp + 64 * 68;   // [c][n] stride 72

    const int tid = threadIdx.x, w = tid >> 5, lane = tid & 31;
    const int g = lane >> 2, tg = lane & 3;
    const int n0 = blockIdx.x * 64, o0 = blockIdx.y * 64;

    float sc[8][4];
#pragma unroll
    for (int nt = 0; nt < 8; nt++)
#pragma unroll
        for (int r = 0; r < 4; r++) sc[nt][r] = 0.f;

    for (int c0 = 0; c0 < CDIM; c0 += 64) {
#pragma unroll
        for (int i = 0; i < 8; i++) {
            int idx = i * 128 + tid, r = idx >> 4, c4 = (idx & 15) << 2;
            float4 v = *(const float4*)(W + (size_t)(o0 + r) * CDIM + c0 + c4);
            float* p = Ws + r * 68 + c4;
            p[0] = __uint_as_float(f2tf(v.x));
            p[1] = __uint_as_float(f2tf(v.y));
            p[2] = __uint_as_float(f2tf(v.z));
            p[3] = __uint_as_float(f2tf(v.w));
        }
#pragma unroll
        for (int i = 0; i < 8; i++) {
            int idx = i * 128 + tid, r = idx >> 4, c4 = (idx & 15) << 2;
            float4 v = *(const float4*)(X + (size_t)(c0 + r) * NSEQ + n0 + c4);
            float* p = Xs + r * 72 + c4;
            p[0] = __uint_as_float(f2tf(v.x));
            p[1] = __uint_as_float(f2tf(v.y));
            p[2] = __uint_as_float(f2tf(v.z));
            p[3] = __uint_as_float(f2tf(v.w));
        }
        __syncthreads();

#pragma unroll
        for (int ks = 0; ks < 8; ks++) {
            const float* xb = Xs + (8 * ks + tg) * 72 + 16 * w + g;
            unsigned a0 = FB(xb[0]), a1 = FB(xb[8]);
            const float* xb2 = xb + 4 * 72;
            unsigned a2 = FB(xb2[0]), a3 = FB(xb2[8]);
#pragma unroll
            for (int nt = 0; nt < 8; nt++) {
                const float* wb = Ws + (g + 8 * nt) * 68 + 8 * ks + tg;
                mma_tf32(sc[nt][0], sc[nt][1], sc[nt][2], sc[nt][3],
                         a0, a1, a2, a3, FB(wb[0]), FB(wb[4]));
            }
        }
        __syncthreads();
    }

    int n = n0 + 16 * w + g;
#pragma unroll
    for (int nt = 0; nt < 8; nt++) {
        int o = o0 + 8 * nt + 2 * tg;
        float b0 = __ldg(bias + o), b1 = __ldg(bias + o + 1);
        __half2 h0 = __floats2half2_rn((sc[nt][0] + b0) * scale,
                                       (sc[nt][1] + b1) * scale);
        __half2 h1 = __floats2half2_rn((sc[nt][2] + b0) * scale,
                                       (sc[nt][3] + b1) * scale);
        *(__half2*)(Yh + (size_t)n * CDIM + o)       = h0;
        *(__half2*)(Yh + (size_t)(n + 8) * CDIM + o) = h1;
    }
}

// ---------------------------------------------------------------------------
// V projection (tf32 MMA).  X[c][n] fp32 -> Y[o][n] fp16 (natural layout)
// via smem-roundtrip transpose epilogue.
// ---------------------------------------------------------------------------
__global__ __launch_bounds__(128) void gemm_vh(
    const float* __restrict__ W, const float* __restrict__ bias,
    const float* __restrict__ X, __half* __restrict__ Yh)
{
    __shared__ float smp[64 * 68 + 64 * 72];
    float* Ws = smp;
    float* Xs = smp + 64 * 68;

    const int tid = threadIdx.x, w = tid >> 5, lane = tid & 31;
    const int g = lane >> 2, tg = lane & 3;
    const int n0 = blockIdx.x * 64, o0 = blockIdx.y * 64;

    float sc[8][4];
#pragma unroll
    for (int nt = 0; nt < 8; nt++)
#pragma unroll
        for (int r = 0; r < 4; r++) sc[nt][r] = 0.f;

    for (int c0 = 0; c0 < CDIM; c0 += 64) {
#pragma unroll
        for (int i = 0; i < 8; i++) {
            int idx = i * 128 + tid, r = idx >> 4, c4 = (idx & 15) << 2;
            float4 v = *(const float4*)(W + (size_t)(o0 + r) * CDIM + c0 + c4);
            float* p = Ws + r * 68 + c4;
            p[0] = __uint_as_float(f2tf(v.x));
            p[1] = __uint_as_float(f2tf(v.y));
            p[2] = __uint_as_float(f2tf(v.z));
            p[3] = __uint_as_float(f2tf(v.w));
        }
#pragma unroll
        for (int i = 0; i < 8; i++) {
            int idx = i * 128 + tid, r = idx >> 4, c4 = (idx & 15) << 2;
            float4 v = *(const float4*)(X + (size_t)(c0 + r) * NSEQ + n0 + c4);
            float* p = Xs + r * 72 + c4;
            p[0] = __uint_as_float(f2tf(v.x));
            p[1] = __uint_as_float(f2tf(v.y));
            p[2] = __uint_as_float(f2tf(v.z));
            p[3] = __uint_as_float(f2tf(v.w));
        }
        __syncthreads();

#pragma unroll
        for (int ks = 0; ks < 8; ks++) {
            const float* xb = Xs + (8 * ks + tg) * 72 + 16 * w + g;
            unsigned a0 = FB(xb[0]), a1 = FB(xb[8]);
            const float* xb2 = xb + 4 * 72;
            unsigned a2 = FB(xb2[0]), a3 = FB(xb2[8]);
#pragma unroll
            for (int nt = 0; nt < 8; nt++) {
                const float* wb = Ws + (g + 8 * nt) * 68 + 8 * ks + tg;
                mma_tf32(sc[nt][0], sc[nt][1], sc[nt][2], sc[nt][3],
                         a0, a1, a2, a3, FB(wb[0]), FB(wb[4]));
            }
        }
        __syncthreads();
    }

    // roundtrip: Ys[n][o] stride 65, then write [o][n] fp16
    float* Ys = smp;
#pragma unroll
    for (int nt = 0; nt < 8; nt++) {
        int n = 16 * w + g, o = 8 * nt + 2 * tg;
        Ys[n * 65 + o]           = sc[nt][0];
        Ys[n * 65 + o + 1]       = sc[nt][1];
        Ys[(n + 8) * 65 + o]     = sc[nt][2];
        Ys[(n + 8) * 65 + o + 1] = sc[nt][3];
    }
    __syncthreads();
#pragma unroll
    for (int i = 0; i < 8; i++) {
        int idx = i * 128 + tid, o = idx & 63, n4 = (idx >> 6) << 2;
        float bb = __ldg(bias + o0 + o);
        __half2 h0 = __floats2half2_rn(Ys[(n4 + 0) * 65 + o] + bb,
                                       Ys[(n4 + 1) * 65 + o] + bb);
        __half2 h1 = __floats2half2_rn(Ys[(n4 + 2) * 65 + o] + bb,
                                       Ys[(n4 + 3) * 65 + o] + bb);
        __half* dst = Yh + (size_t)(o0 + o) * NSEQ + n0 + n4;
        *(__half2*)(dst)     = h0;
        *(__half2*)(dst + 2) = h1;
    }
}

// ---------------------------------------------------------------------------
// Final O projection (tf32 MMA).  X[n][c] fp32; output Y[o][n] fp32.
// ---------------------------------------------------------------------------
__global__ __launch_bounds__(128) void gemm_oproj(
    const float* __restrict__ W, const float* __restrict__ bias,
    const float* __restrict__ X, float* __restrict__ Y)
{
    __shared__ float smp[64 * 68 + 64 * 68];
    float* Ws = smp;             // [o][c] stride 68
    float* Xs = smp + 64 * 68;   // [n][c] stride 68

    const int tid = threadIdx.x, w = tid >> 5, lane = tid & 31;
    const int g = lane >> 2, tg = lane & 3;
    const int n0 = blockIdx.x * 64, o0 = blockIdx.y * 64;

    float sc[8][4];
#pragma unroll
    for (int nt = 0; nt < 8; nt++)
#pragma unroll
        for (int r = 0; r < 4; r++) sc[nt][r] = 0.f;

    for (int c0 = 0; c0 < CDIM; c0 += 64) {
#pragma unroll
        for (int i = 0; i < 8; i++) {
            int idx = i * 128 + tid, r = idx >> 4, c4 = (idx & 15) << 2;
            float4 v = *(const float4*)(W + (size_t)(o0 + r) * CDIM + c0 + c4);
            float* p = Ws + r * 68 + c4;
            p[0] = __uint_as_float(f2tf(v.x));
            p[1] = __uint_as_float(f2tf(v.y));
            p[2] = __uint_as_float(f2tf(v.z));
            p[3] = __uint_as_float(f2tf(v.w));
        }
#pragma unroll
        for (int i = 0; i < 8; i++) {
            int idx = i * 128 + tid, r = idx >> 4, c4 = (idx & 15) << 2;
            float4 v = *(const float4*)(X + (size_t)(n0 + r) * CDIM + c0 + c4);
            float* p = Xs + r * 68 + c4;
            p[0] = __uint_as_float(f2tf(v.x));
            p[1] = __uint_as_float(f2tf(v.y));
            p[2] = __uint_as_float(f2tf(v.z));
            p[3] = __uint_as_float(f2tf(v.w));
        }
        __syncthreads();

#pragma unroll
        for (int ks = 0; ks < 8; ks++) {
            const float* xb = Xs + (16 * w + g) * 68 + 8 * ks;
            unsigned a0 = FB(xb[tg]),     a1 = FB(xb[8 * 68 + tg]);
            unsigned a2 = FB(xb[tg + 4]), a3 = FB(xb[8 * 68 + tg + 4]);
#pragma unroll
            for (int nt = 0; nt < 8; nt++) {
                const float* wb = Ws + (g + 8 * nt) * 68 + 8 * ks + tg;
                mma_tf32(sc[nt][0], sc[nt][1], sc[nt][2], sc[nt][3],
                         a0, a1, a2, a3, FB(wb[0]), FB(wb[4]));
            }
        }
        __syncthreads();
    }

    float* Ys = smp;  // [n][o] stride 65
#pragma unroll
    for (int nt = 0; nt < 8; nt++) {
        int n = 16 * w + g, o = 8 * nt + 2 * tg;
        Ys[n * 65 + o]           = sc[nt][0];
        Ys[n * 65 + o + 1]       = sc[nt][1];
        Ys[(n + 8) * 65 + o]     = sc[nt][2];
        Ys[(n + 8) * 65 + o + 1] = sc[nt][3];
    }
    __syncthreads();
#pragma unroll
    for (int i = 0; i < 8; i++) {
        int idx = i * 128 + tid, o = idx & 63, n4 = (idx >> 6) << 2;
        float bb = __ldg(bias + o0 + o);
        float4 v;
        v.x = Ys[(n4 + 0) * 65 + o] + bb;
        v.y = Ys[(n4 + 1) * 65 + o] + bb;
        v.z = Ys[(n4 + 2) * 65 + o] + bb;
        v.w = Ys[(n4 + 3) * 65 + o] + bb;
        *(float4*)(Y + (size_t)(o0 + o) * NSEQ + n0 + n4) = v;
    }
}

// ---------------------------------------------------------------------------
// fp16 m16n8k16 flash attention (log2-domain softmax, fp32 accumulate).
// QT,KT: fp16 [n][c]; VT: fp16 [c][n]; AO: fp32 [n][c].
// grid (64, 8 heads), 128 thr, __launch_bounds__(128,4).
// Key property: S C-frags ARE the PV B-frags on the same lane (no shuffles).
// Smem strides 72 halfs: 36 == 4 mod 32 -> all frag LDS bank-conflict-free.
// ---------------------------------------------------------------------------
__global__ __launch_bounds__(128, 4) void attn_h(
    const __half* __restrict__ QT, const __half* __restrict__ KT,
    const __half* __restrict__ VT, float* __restrict__ AO)
{
    __shared__ __half Qh[64 * 72];   // [q][c]
    __shared__ __half Kh[64 * 72];   // [key][c]
    __shared__ __half Vh[64 * 72];   // [d][key]

    const int tid  = threadIdx.x;
    const int w    = tid >> 5, lane = tid & 31;
    const int g    = lane >> 2, tg = lane & 3;
    const int q0   = blockIdx.x * 64;
    const int hb   = blockIdx.y * 64;
    const unsigned FULL = 0xffffffffu;

    const uint32_t qh_u = (uint32_t)__cvta_generic_to_shared(Qh);
    const uint32_t kh_u = (uint32_t)__cvta_generic_to_shared(Kh);
    const uint32_t vh_u = (uint32_t)__cvta_generic_to_shared(Vh);

    // ---- prologue: Q + K_0 + V_0 (fp16, 16B = 8 halfs per cp) ----
#pragma unroll
    for (int i = 0; i < 4; i++) {
        int idx = i * 128 + tid, r = idx >> 3, ch = (idx & 7) << 3;
        cp16(qh_u + (r * 72 + ch) * 2, QT + (size_t)(q0 + r) * CDIM + hb + ch);
        cp16(kh_u + (r * 72 + ch) * 2, KT + (size_t)r * CDIM + hb + ch);
        cp16(vh_u + (r * 72 + ch) * 2, VT + (size_t)(hb + r) * NSEQ + ch);
    }
    cp_commit();
    cp_wait0();
    __syncthreads();

    float m0 = -1e30f, m1 = -1e30f, l0 = 0.f, l1 = 0.f;
    float oa[4][2][4];
#pragma unroll
    for (int mt = 0; mt < 4; mt++)
#pragma unroll
        for (int np = 0; np < 2; np++)
#pragma unroll
            for (int r = 0; r < 4; r++) oa[mt][np][r] = 0.f;

    const __half* qb = Qh + (16 * w + g) * 72;

    for (int it = 0; it < 64; it++) {
        const int t0 = it * 64;

        // ---- S = Q K^T (4 ksteps of 16, 8 n-tiles) ----
        float sc[8][4];
#pragma unroll
        for (int nt = 0; nt < 8; nt++)
#pragma unroll
            for (int r = 0; r < 4; r++) sc[nt][r] = 0.f;

#pragma unroll
        for (int ks = 0; ks < 4; ks++) {
            const __half* qa = qb + 16 * ks + 2 * tg;
            unsigned a0 = *(const unsigned*)(qa);
            unsigned a1 = *(const unsigned*)(qa + 8 * 72);
            unsigned a2 = *(const unsigned*)(qa + 8);
            unsigned a3 = *(const unsigned*)(qa + 8 * 72 + 8);
#pragma unroll
            for (int nt = 0; nt < 8; nt++) {
                const __half* kb = Kh + (8 * nt + g) * 72 + 16 * ks + 2 * tg;
                unsigned b0 = *(const unsigned*)(kb);
                unsigned b1 = *(const unsigned*)(kb + 8);
                mma_f16(sc[nt][0], sc[nt][1], sc[nt][2], sc[nt][3],
                        a0, a1, a2, a3, b0, b1);
            }
        }

        cp_wait0();        // V_t complete
        __syncthreads();   // Kh free; Vh published

        if (it < 63) {     // prefetch K_{t+1}
            const __half* kn = KT + (size_t)(t0 + 64) * CDIM + hb;
#pragma unroll
            for (int i = 0; i < 4; i++) {
                int idx = i * 128 + tid, r = idx >> 3, ch = (idx & 7) << 3;
                cp16(kh_u + (r * 72 + ch) * 2, kn + (size_t)r * CDIM + ch);
            }
            cp_commit();
        }

        // ---- online softmax (log2 domain) ----
        float mx0 = -1e30f, mx1 = -1e30f;
#pragma unroll
        for (int nt = 0; nt < 8; nt++) {
            mx0 = fmaxf(mx0, fmaxf(sc[nt][0], sc[nt][1]));
            mx1 = fmaxf(mx1, fmaxf(sc[nt][2], sc[nt][3]));
        }
        mx0 = fmaxf(mx0, __shfl_xor_sync(FULL, mx0, 1));
        mx0 = fmaxf(mx0, __shfl_xor_sync(FULL, mx0, 2));
        mx1 = fmaxf(mx1, __shfl_xor_sync(FULL, mx1, 1));
        mx1 = fmaxf(mx1, __shfl_xor_sync(FULL, mx1, 2));

        float nm0 = fmaxf(m0, mx0), nm1 = fmaxf(m1, mx1);
        float al0 = ex2f(m0 - nm0), al1 = ex2f(m1 - nm1);
        float s0 = 0.f, s1 = 0.f;
#pragma unroll
        for (int nt = 0; nt < 8; nt++) {
            sc[nt][0] = ex2f(sc[nt][0] - nm0);
            sc[nt][1] = ex2f(sc[nt][1] - nm0);
            sc[nt][2] = ex2f(sc[nt][2] - nm1);
            sc[nt][3] = ex2f(sc[nt][3] - nm1);
            s0 += sc[nt][0] + sc[nt][1];
            s1 += sc[nt][2] + sc[nt][3];
        }
        s0 += __shfl_xor_sync(FULL, s0, 1);
        s0 += __shfl_xor_sync(FULL, s0, 2);
        s1 += __shfl_xor_sync(FULL, s1, 1);
        s1 += __shfl_xor_sync(FULL, s1, 2);
        l0 = l0 * al0 + s0;
        l1 = l1 * al1 + s1;
        m0 = nm0; m1 = nm1;

        // ---- pack P into fp16 B-frags: SAME LANE, no shuffles ----
        unsigned p0[8], p1[8];
#pragma unroll
        for (int nt = 0; nt < 8; nt++) {
            __half2 h0 = __floats2half2_rn(sc[nt][0], sc[nt][1]);
            __half2 h1 = __floats2half2_rn(sc[nt][2], sc[nt][3]);
            p0[nt] = H2U(h0);
            p1[nt] = H2U(h1);
        }

        // ---- rescale O accumulators ----
        float av00 = __shfl_sync(FULL, al0, (2 * tg) << 2);
        float av01 = __shfl_sync(FULL, al0, (2 * tg + 1) << 2);
        float av10 = __shfl_sync(FULL, al1, (2 * tg) << 2);
        float av11 = __shfl_sync(FULL, al1, (2 * tg + 1) << 2);
#pragma unroll
        for (int mt = 0; mt < 4; mt++) {
            oa[mt][0][0] *= av00; oa[mt][0][1] *= av01;
            oa[mt][0][2] *= av00; oa[mt][0][3] *= av01;
            oa[mt][1][0] *= av10; oa[mt][1][1] *= av11;
            oa[mt][1][2] *= av10; oa[mt][1][3] *= av11;
        }

        // ---- O^T += V^T P^T (A from Vh[d][k], B = packed P) ----
#pragma unroll
        for (int ks = 0; ks < 4; ks++) {
            unsigned bq0 = p0[2 * ks], bq1 = p0[2 * ks + 1];
            unsigned br0 = p1[2 * ks], br1 = p1[2 * ks + 1];
#pragma unroll
            for (int mt = 0; mt < 4; mt++) {
                const __half* va = Vh + (16 * mt + g) * 72 + 16 * ks + 2 * tg;
                unsigned a0 = *(const unsigned*)(va);
                unsigned a1 = *(const unsigned*)(va + 8 * 72);
                unsigned a2 = *(const unsigned*)(va + 8);
                unsigned a3 = *(const unsigned*)(va + 8 * 72 + 8);
                mma_f16(oa[mt][0][0], oa[mt][0][1], oa[mt][0][2], oa[mt][0][3],
                        a0, a1, a2, a3, bq0, bq1);
                mma_f16(oa[mt][1][0], oa[mt][1][1], oa[mt][1][2], oa[mt][1][3],
                        a0, a1, a2, a3, br0, br1);
            }
        }

        cp_wait0();        // K_{t+1} complete
        __syncthreads();   // Vh free; Kh published

        if (it < 63) {     // prefetch V_{t+1}
            const __half* vn = VT + (size_t)hb * NSEQ + t0 + 64;
#pragma unroll
            for (int i = 0; i < 4; i++) {
                int idx = i * 128 + tid, r = idx >> 3, ch = (idx & 7) << 3;
                cp16(vh_u + (r * 72 + ch) * 2, vn + (size_t)r * NSEQ + ch);
            }
            cp_commit();
        }
    }

    // ---- normalize, store to AO[n][c] ----
    float inv0 = 1.f / l0, inv1 = 1.f / l1;
    float n00 = __shfl_sync(FULL, inv0, (2 * tg) << 2);
    float n01 = __shfl_sync(FULL, inv0, (2 * tg + 1) << 2);
    float n10 = __shfl_sync(FULL, inv1, (2 * tg) << 2);
    float n11 = __shfl_sync(FULL, inv1, (2 * tg + 1) << 2);

#pragma unroll
    for (int mt = 0; mt < 4; mt++) {
#pragma unroll
        for (int np = 0; np < 2; np++) {
            float sa = np ? n10 : n00;
            float sb = np ? n11 : n01;
            int qa = q0 + 16 * w + 8 * np + 2 * tg;
            int d  = hb + 16 * mt + g;
            AO[(size_t)qa * CDIM + d]           = oa[mt][np][0] * sa;
            AO[(size_t)(qa + 1) * CDIM + d]     = oa[mt][np][1] * sb;
            AO[(size_t)qa * CDIM + d + 8]       = oa[mt][np][2] * sa;
            AO[(size_t)(qa + 1) * CDIM + d + 8] = oa[mt][np][3] * sb;
        }
    }
}

// ---------------------------------------------------------------------------
extern "C" void kernel_launch(void* const* d_in, const int* in_sizes, int n_in,
                              void* d_out, int out_size)
{
    const float* x   = (const float*)d_in[0];
    const float* q_w = (const float*)d_in[1];
    const float* q_b = (const float*)d_in[2];
    const float* k_w = (const float*)d_in[3];
    const float* k_b = (const float*)d_in[4];
    const float* v_w = (const float*)d_in[5];
    const float* v_b = (const float*)d_in[6];
    const float* o_w = (const float*)d_in[7];
    const float* o_b = (const float*)d_in[8];
    float* out = (float*)d_out;

    __half *gq, *gk, *gv;
    float *gao;
    cudaGetSymbolAddress((void**)&gq,  g_q);
    cudaGetSymbolAddress((void**)&gk,  g_k);
    cudaGetSymbolAddress((void**)&gv,  g_v);
    cudaGetSymbolAddress((void**)&gao, g_ao);

    // HEAD_DIM^-0.5 * log2(e): K projection pre-scales logits into log2 domain
    const float kSCALE = 0.125f * 1.4426950408889634f;

    dim3 pgrid(NSEQ / 64, CDIM / 64);
    gemm_qk<<<pgrid, 128>>>(q_w, q_b, x, gq, 1.0f);
    gemm_qk<<<pgrid, 128>>>(k_w, k_b, x, gk, kSCALE);
    gemm_vh<<<pgrid, 128>>>(v_w, v_b, x, gv);

    dim3 agrid(NSEQ / 64, 8);
    attn_h<<<agrid, 128>>>(gq, gk, gv, gao);

    gemm_oproj<<<pgrid, 128>>>(o_w, o_b, gao, out);
}

// round 12
// speedup vs baseline: 6.6171x; 1.1175x over previous
#include <cuda_runtime.h>
#include <cuda_fp16.h>
#include <cstdint>

#define NSEQ 4096
#define CDIM 512

// Scratch (allocation-free rule: __device__ globals)
__device__ __half g_q[CDIM * NSEQ];   // Q^T [n][c] fp16
__device__ __half g_k[CDIM * NSEQ];   // K^T [n][c] fp16, scaled by 0.125*log2e
__device__ __half g_v[CDIM * NSEQ];   // V   [c][n] fp16 (natural)
__device__ float  g_ao[CDIM * NSEQ];  // attention out [n][c] fp32

__device__ __forceinline__ float ex2f(float x) {
    float y; asm("ex2.approx.f32 %0, %1;" : "=f"(y) : "f"(x)); return y;
}
__device__ __forceinline__ void cp16(uint32_t dst, const void* src) {
    asm volatile("cp.async.cg.shared.global [%0], [%1], 16;" :: "r"(dst), "l"(src));
}
__device__ __forceinline__ void cp_commit() { asm volatile("cp.async.commit_group;"); }
__device__ __forceinline__ void cp_wait0()  { asm volatile("cp.async.wait_group 0;" ::: "memory"); }

__device__ __forceinline__ void mma_f16(
    float& c0, float& c1, float& c2, float& c3,
    unsigned a0, unsigned a1, unsigned a2, unsigned a3,
    unsigned b0, unsigned b1)
{
    asm volatile(
        "mma.sync.aligned.m16n8k16.row.col.f32.f16.f16.f32 "
        "{%0,%1,%2,%3},{%4,%5,%6,%7},{%8,%9},{%0,%1,%2,%3};"
        : "+f"(c0), "+f"(c1), "+f"(c2), "+f"(c3)
        : "r"(a0), "r"(a1), "r"(a2), "r"(a3), "r"(b0), "r"(b1));
}
#define H2U(h) (*(const unsigned*)&(h))

// ---------------------------------------------------------------------------
// fp16 m16n8k16 projection GEMM.  W[o][c] fp32, bias[o] fp32.
// A = W (m=o), B = X (n=n), C[o][n] fp32 accumulate.
// MODE 0: X=[c][n] fp32 (hidden); out Yh[n][o] fp16 = (C+b)*scale  (Q,K)
// MODE 1: X=[c][n] fp32 (hidden); out Yh[o][n] fp16 = C+b           (V)
// MODE 2: X=[n][c] fp32 (AO);     out Yf[o][n] fp32 = C+b           (O)
// B for modes 0/1 via half2 c-pair interleave: Xsh2[c/2][n]={X[c][n],X[c+1][n]}
//   -> every B-frag is ONE 32-bit LDS, banks 4*tg+g (conflict-free).
// Mode 2: AO[n][c] is already k-contiguous B layout -> direct.
// ---------------------------------------------------------------------------
template<int MODE>
__global__ __launch_bounds__(128) void gemm_h(
    const float* __restrict__ W, const float* __restrict__ bias,
    const float* __restrict__ Xf, __half* __restrict__ Yh,
    float* __restrict__ Yf, float scale)
{
    __shared__ __align__(16) char smbuf[18432];
    __half*  Wsh  = (__half*)smbuf;             // [o][c] stride 72 halfs (9216 B)
    __half*  Bsh  = (__half*)(smbuf + 9216);    // MODE2: [n][c] stride 72 halfs
    __half2* Xsh2 = (__half2*)(smbuf + 9216);   // MODE0/1: [c/2][n] stride 68 h2

    const int tid = threadIdx.x, w = tid >> 5, lane = tid & 31;
    const int g = lane >> 2, tg = lane & 3;
    const int n0 = blockIdx.x * 64, o0 = blockIdx.y * 64;

    float sc[8][4];
#pragma unroll
    for (int nt = 0; nt < 8; nt++)
#pragma unroll
        for (int r = 0; r < 4; r++) sc[nt][r] = 0.f;

    for (int c0 = 0; c0 < CDIM; c0 += 64) {
        // ---- W tile: fp32 -> fp16 [o][c]@72 ----
#pragma unroll
        for (int i = 0; i < 8; i++) {
            int idx = i * 128 + tid, r = idx >> 4, c4 = (idx & 15) << 2;
            float4 v = *(const float4*)(W + (size_t)(o0 + r) * CDIM + c0 + c4);
            __half2 h0 = __floats2half2_rn(v.x, v.y);
            __half2 h1 = __floats2half2_rn(v.z, v.w);
            uint2 pk = make_uint2(H2U(h0), H2U(h1));
            *(uint2*)(Wsh + r * 72 + c4) = pk;
        }
        // ---- B tile ----
        if (MODE < 2) {
            // X[c][n] fp32 -> interleaved half2 [c/2][n]@68
#pragma unroll
            for (int i = 0; i < 4; i++) {
                int idx = i * 128 + tid, r2 = idx >> 4, n4 = (idx & 15) << 2;
                const float* pa = Xf + (size_t)(c0 + 2 * r2) * NSEQ + n0 + n4;
                float4 a = *(const float4*)(pa);
                float4 b = *(const float4*)(pa + NSEQ);
                __half2 h0 = __floats2half2_rn(a.x, b.x);
                __half2 h1 = __floats2half2_rn(a.y, b.y);
                __half2 h2 = __floats2half2_rn(a.z, b.z);
                __half2 h3 = __floats2half2_rn(a.w, b.w);
                uint4 pk = make_uint4(H2U(h0), H2U(h1), H2U(h2), H2U(h3));
                *(uint4*)(Xsh2 + r2 * 68 + n4) = pk;
            }
        } else {
            // AO[n][c] fp32 -> fp16 [n][c]@72
#pragma unroll
            for (int i = 0; i < 8; i++) {
                int idx = i * 128 + tid, r = idx >> 4, c4 = (idx & 15) << 2;
                float4 v = *(const float4*)(Xf + (size_t)(n0 + r) * CDIM + c0 + c4);
                __half2 h0 = __floats2half2_rn(v.x, v.y);
                __half2 h1 = __floats2half2_rn(v.z, v.w);
                uint2 pk = make_uint2(H2U(h0), H2U(h1));
                *(uint2*)(Bsh + r * 72 + c4) = pk;
            }
        }
        __syncthreads();

        // ---- 32 MMAs per chunk ----
#pragma unroll
        for (int ks = 0; ks < 4; ks++) {
            const __half* wa = Wsh + (16 * w + g) * 72 + 16 * ks + 2 * tg;
            unsigned a0 = *(const unsigned*)(wa);
            unsigned a1 = *(const unsigned*)(wa + 8 * 72);
            unsigned a2 = *(const unsigned*)(wa + 8);
            unsigned a3 = *(const unsigned*)(wa + 8 * 72 + 8);
#pragma unroll
            for (int nt = 0; nt < 8; nt++) {
                unsigned b0, b1;
                if (MODE < 2) {
                    b0 = H2U(Xsh2[(8 * ks + tg) * 68 + 8 * nt + g]);
                    b1 = H2U(Xsh2[(8 * ks + tg + 4) * 68 + 8 * nt + g]);
                } else {
                    const __half* bb = Bsh + (8 * nt + g) * 72 + 16 * ks + 2 * tg;
                    b0 = *(const unsigned*)(bb);
                    b1 = *(const unsigned*)(bb + 8);
                }
                mma_f16(sc[nt][0], sc[nt][1], sc[nt][2], sc[nt][3],
                        a0, a1, a2, a3, b0, b1);
            }
        }
        __syncthreads();
    }

    const int oA = 16 * w + g, oB = oA + 8;
    const float bA = __ldg(bias + o0 + oA), bB = __ldg(bias + o0 + oB);

    if (MODE == 0) {
        // transposed fp16 out via fp32 smem roundtrip: Ys[n][o] stride 65
        float* Ys = (float*)smbuf;
#pragma unroll
        for (int nt = 0; nt < 8; nt++) {
            int n = 8 * nt + 2 * tg;
            Ys[n * 65 + oA]       = (sc[nt][0] + bA) * scale;
            Ys[(n + 1) * 65 + oA] = (sc[nt][1] + bA) * scale;
            Ys[n * 65 + oB]       = (sc[nt][2] + bB) * scale;
            Ys[(n + 1) * 65 + oB] = (sc[nt][3] + bB) * scale;
        }
        __syncthreads();
#pragma unroll
        for (int i = 0; i < 4; i++) {
            int idx = i * 128 + tid, n = idx >> 3, o8 = (idx & 7) << 3;
            const float* src = Ys + n * 65 + o8;
            __half2 h0 = __floats2half2_rn(src[0], src[1]);
            __half2 h1 = __floats2half2_rn(src[2], src[3]);
            __half2 h2 = __floats2half2_rn(src[4], src[5]);
            __half2 h3 = __floats2half2_rn(src[6], src[7]);
            uint4 pk = make_uint4(H2U(h0), H2U(h1), H2U(h2), H2U(h3));
            *(uint4*)(Yh + (size_t)(n0 + n) * CDIM + o0 + o8) = pk;
        }
    } else if (MODE == 1) {
        // natural fp16 out [o][n], direct from C-frags
#pragma unroll
        for (int nt = 0; nt < 8; nt++) {
            int n = 8 * nt + 2 * tg;
            __half2 hA = __floats2half2_rn(sc[nt][0] + bA, sc[nt][1] + bA);
            __half2 hB = __floats2half2_rn(sc[nt][2] + bB, sc[nt][3] + bB);
            *(__half2*)(Yh + (size_t)(o0 + oA) * NSEQ + n0 + n) = hA;
            *(__half2*)(Yh + (size_t)(o0 + oB) * NSEQ + n0 + n) = hB;
        }
    } else {
        // natural fp32 out [o][n], direct from C-frags
#pragma unroll
        for (int nt = 0; nt < 8; nt++) {
            int n = 8 * nt + 2 * tg;
            float2 vA = make_float2(sc[nt][0] + bA, sc[nt][1] + bA);
            float2 vB = make_float2(sc[nt][2] + bB, sc[nt][3] + bB);
            *(float2*)(Yf + (size_t)(o0 + oA) * NSEQ + n0 + n) = vA;
            *(float2*)(Yf + (size_t)(o0 + oB) * NSEQ + n0 + n) = vB;
        }
    }
}

// ---------------------------------------------------------------------------
// fp16 m16n8k16 flash attention (log2-domain softmax, fp32 accumulate).
// QT,KT: fp16 [n][c]; VT: fp16 [c][n]; AO: fp32 [n][c].
// grid (64, 8 heads), 128 thr, __launch_bounds__(128,4).
// S C-frags ARE the PV B-frags on the same lane (no shuffles).
// ---------------------------------------------------------------------------
__global__ __launch_bounds__(128, 4) void attn_h(
    const __half* __restrict__ QT, const __half* __restrict__ KT,
    const __half* __restrict__ VT, float* __restrict__ AO)
{
    __shared__ __half Qh[64 * 72];   // [q][c]
    __shared__ __half Kh[64 * 72];   // [key][c]
    __shared__ __half Vh[64 * 72];   // [d][key]

    const int tid  = threadIdx.x;
    const int w    = tid >> 5, lane = tid & 31;
    const int g    = lane >> 2, tg = lane & 3;
    const int q0   = blockIdx.x * 64;
    const int hb   = blockIdx.y * 64;
    const unsigned FULL = 0xffffffffu;

    const uint32_t qh_u = (uint32_t)__cvta_generic_to_shared(Qh);
    const uint32_t kh_u = (uint32_t)__cvta_generic_to_shared(Kh);
    const uint32_t vh_u = (uint32_t)__cvta_generic_to_shared(Vh);

    // ---- prologue: Q + K_0 + V_0 ----
#pragma unroll
    for (int i = 0; i < 4; i++) {
        int idx = i * 128 + tid, r = idx >> 3, ch = (idx & 7) << 3;
        cp16(qh_u + (r * 72 + ch) * 2, QT + (size_t)(q0 + r) * CDIM + hb + ch);
        cp16(kh_u + (r * 72 + ch) * 2, KT + (size_t)r * CDIM + hb + ch);
        cp16(vh_u + (r * 72 + ch) * 2, VT + (size_t)(hb + r) * NSEQ + ch);
    }
    cp_commit();
    cp_wait0();
    __syncthreads();

    float m0 = -1e30f, m1 = -1e30f, l0 = 0.f, l1 = 0.f;
    float oa[4][2][4];
#pragma unroll
    for (int mt = 0; mt < 4; mt++)
#pragma unroll
        for (int np = 0; np < 2; np++)
#pragma unroll
            for (int r = 0; r < 4; r++) oa[mt][np][r] = 0.f;

    const __half* qb = Qh + (16 * w + g) * 72;

    for (int it = 0; it < 64; it++) {
        const int t0 = it * 64;

        // ---- S = Q K^T ----
        float sc[8][4];
#pragma unroll
        for (int nt = 0; nt < 8; nt++)
#pragma unroll
            for (int r = 0; r < 4; r++) sc[nt][r] = 0.f;

#pragma unroll
        for (int ks = 0; ks < 4; ks++) {
            const __half* qa = qb + 16 * ks + 2 * tg;
            unsigned a0 = *(const unsigned*)(qa);
            unsigned a1 = *(const unsigned*)(qa + 8 * 72);
            unsigned a2 = *(const unsigned*)(qa + 8);
            unsigned a3 = *(const unsigned*)(qa + 8 * 72 + 8);
#pragma unroll
            for (int nt = 0; nt < 8; nt++) {
                const __half* kb = Kh + (8 * nt + g) * 72 + 16 * ks + 2 * tg;
                unsigned b0 = *(const unsigned*)(kb);
                unsigned b1 = *(const unsigned*)(kb + 8);
                mma_f16(sc[nt][0], sc[nt][1], sc[nt][2], sc[nt][3],
                        a0, a1, a2, a3, b0, b1);
            }
        }

        cp_wait0();
        __syncthreads();

        if (it < 63) {     // prefetch K_{t+1}
            const __half* kn = KT + (size_t)(t0 + 64) * CDIM + hb;
#pragma unroll
            for (int i = 0; i < 4; i++) {
                int idx = i * 128 + tid, r = idx >> 3, ch = (idx & 7) << 3;
                cp16(kh_u + (r * 72 + ch) * 2, kn + (size_t)r * CDIM + ch);
            }
            cp_commit();
        }

        // ---- online softmax (log2 domain) ----
        float mx0 = -1e30f, mx1 = -1e30f;
#pragma unroll
        for (int nt = 0; nt < 8; nt++) {
            mx0 = fmaxf(mx0, fmaxf(sc[nt][0], sc[nt][1]));
            mx1 = fmaxf(mx1, fmaxf(sc[nt][2], sc[nt][3]));
        }
        mx0 = fmaxf(mx0, __shfl_xor_sync(FULL, mx0, 1));
        mx0 = fmaxf(mx0, __shfl_xor_sync(FULL, mx0, 2));
        mx1 = fmaxf(mx1, __shfl_xor_sync(FULL, mx1, 1));
        mx1 = fmaxf(mx1, __shfl_xor_sync(FULL, mx1, 2));

        float nm0 = fmaxf(m0, mx0), nm1 = fmaxf(m1, mx1);
        float al0 = ex2f(m0 - nm0), al1 = ex2f(m1 - nm1);
        float s0 = 0.f, s1 = 0.f;
#pragma unroll
        for (int nt = 0; nt < 8; nt++) {
            sc[nt][0] = ex2f(sc[nt][0] - nm0);
            sc[nt][1] = ex2f(sc[nt][1] - nm0);
            sc[nt][2] = ex2f(sc[nt][2] - nm1);
            sc[nt][3] = ex2f(sc[nt][3] - nm1);
            s0 += sc[nt][0] + sc[nt][1];
            s1 += sc[nt][2] + sc[nt][3];
        }
        s0 += __shfl_xor_sync(FULL, s0, 1);
        s0 += __shfl_xor_sync(FULL, s0, 2);
        s1 += __shfl_xor_sync(FULL, s1, 1);
        s1 += __shfl_xor_sync(FULL, s1, 2);
        l0 = l0 * al0 + s0;
        l1 = l1 * al1 + s1;
        m0 = nm0; m1 = nm1;

        // ---- pack P into fp16 B-frags: SAME LANE, no shuffles ----
        unsigned p0[8], p1[8];
#pragma unroll
        for (int nt = 0; nt < 8; nt++) {
            __half2 h0 = __floats2half2_rn(sc[nt][0], sc[nt][1]);
            __half2 h1 = __floats2half2_rn(sc[nt][2], sc[nt][3]);
            p0[nt] = H2U(h0);
            p1[nt] = H2U(h1);
        }

        // ---- rescale O accumulators ----
        float av00 = __shfl_sync(FULL, al0, (2 * tg) << 2);
        float av01 = __shfl_sync(FULL, al0, (2 * tg + 1) << 2);
        float av10 = __shfl_sync(FULL, al1, (2 * tg) << 2);
        float av11 = __shfl_sync(FULL, al1, (2 * tg + 1) << 2);
#pragma unroll
        for (int mt = 0; mt < 4; mt++) {
            oa[mt][0][0] *= av00; oa[mt][0][1] *= av01;
            oa[mt][0][2] *= av00; oa[mt][0][3] *= av01;
            oa[mt][1][0] *= av10; oa[mt][1][1] *= av11;
            oa[mt][1][2] *= av10; oa[mt][1][3] *= av11;
        }

        // ---- O^T += V^T P^T ----
#pragma unroll
        for (int ks = 0; ks < 4; ks++) {
            unsigned bq0 = p0[2 * ks], bq1 = p0[2 * ks + 1];
            unsigned br0 = p1[2 * ks], br1 = p1[2 * ks + 1];
#pragma unroll
            for (int mt = 0; mt < 4; mt++) {
                const __half* va = Vh + (16 * mt + g) * 72 + 16 * ks + 2 * tg;
                unsigned a0 = *(const unsigned*)(va);
                unsigned a1 = *(const unsigned*)(va + 8 * 72);
                unsigned a2 = *(const unsigned*)(va + 8);
                unsigned a3 = *(const unsigned*)(va + 8 * 72 + 8);
                mma_f16(oa[mt][0][0], oa[mt][0][1], oa[mt][0][2], oa[mt][0][3],
                        a0, a1, a2, a3, bq0, bq1);
                mma_f16(oa[mt][1][0], oa[mt][1][1], oa[mt][1][2], oa[mt][1][3],
                        a0, a1, a2, a3, br0, br1);
            }
        }

        cp_wait0();
        __syncthreads();

        if (it < 63) {     // prefetch V_{t+1}
            const __half* vn = VT + (size_t)hb * NSEQ + t0 + 64;
#pragma unroll
            for (int i = 0; i < 4; i++) {
                int idx = i * 128 + tid, r = idx >> 3, ch = (idx & 7) << 3;
                cp16(vh_u + (r * 72 + ch) * 2, vn + (size_t)r * NSEQ + ch);
            }
            cp_commit();
        }
    }

    // ---- normalize, store to AO[n][c] ----
    float inv0 = 1.f / l0, inv1 = 1.f / l1;
    float n00 = __shfl_sync(FULL, inv0, (2 * tg) << 2);
    float n01 = __shfl_sync(FULL, inv0, (2 * tg + 1) << 2);
    float n10 = __shfl_sync(FULL, inv1, (2 * tg) << 2);
    float n11 = __shfl_sync(FULL, inv1, (2 * tg + 1) << 2);

#pragma unroll
    for (int mt = 0; mt < 4; mt++) {
#pragma unroll
        for (int np = 0; np < 2; np++) {
            float sa = np ? n10 : n00;
            float sb = np ? n11 : n01;
            int qa = q0 + 16 * w + 8 * np + 2 * tg;
            int d  = hb + 16 * mt + g;
            AO[(size_t)qa * CDIM + d]           = oa[mt][np][0] * sa;
            AO[(size_t)(qa + 1) * CDIM + d]     = oa[mt][np][1] * sb;
            AO[(size_t)qa * CDIM + d + 8]       = oa[mt][np][2] * sa;
            AO[(size_t)(qa + 1) * CDIM + d + 8] = oa[mt][np][3] * sb;
        }
    }
}

// ---------------------------------------------------------------------------
extern "C" void kernel_launch(void* const* d_in, const int* in_sizes, int n_in,
                              void* d_out, int out_size)
{
    const float* x   = (const float*)d_in[0];
    const float* q_w = (const float*)d_in[1];
    const float* q_b = (const float*)d_in[2];
    const float* k_w = (const float*)d_in[3];
    const float* k_b = (const float*)d_in[4];
    const float* v_w = (const float*)d_in[5];
    const float* v_b = (const float*)d_in[6];
    const float* o_w = (const float*)d_in[7];
    const float* o_b = (const float*)d_in[8];
    float* out = (float*)d_out;

    __half *gq, *gk, *gv;
    float *gao;
    cudaGetSymbolAddress((void**)&gq,  g_q);
    cudaGetSymbolAddress((void**)&gk,  g_k);
    cudaGetSymbolAddress((void**)&gv,  g_v);
    cudaGetSymbolAddress((void**)&gao, g_ao);

    // HEAD_DIM^-0.5 * log2(e): K projection pre-scales logits into log2 domain
    const float kSCALE = 0.125f * 1.4426950408889634f;

    dim3 pgrid(NSEQ / 64, CDIM / 64);
    gemm_h<0><<<pgrid, 128>>>(q_w, q_b, x, gq, nullptr, 1.0f);
    gemm_h<0><<<pgrid, 128>>>(k_w, k_b, x, gk, nullptr, kSCALE);
    gemm_h<1><<<pgrid, 128>>>(v_w, v_b, x, gv, nullptr, 1.0f);

    dim3 agrid(NSEQ / 64, 8);
    attn_h<<<agrid, 128>>>(gq, gk, gv, gao);

    gemm_h<2><<<pgrid, 128>>>(o_w, o_b, gao, nullptr, out, 1.0f);
}